// round 5
// baseline (speedup 1.0000x reference)
#include <cuda_runtime.h>
#include <math.h>

#define LL 2
#define B 8
#define S 2048
#define D 2048
#define NH 16
#define HD 128
#define DC 4096
#define II 16384
#define PADTOK 50257

// ---------------- scratch (no allocation allowed) ----------------
__device__ int   g_idx[B];
__device__ float g_mean[LL][B][S];
__device__ float g_rstd[LL][B][S];
__device__ float g_qh[LL][B][D];
__device__ float g_q[LL][B][D];
__device__ float g_Kg[LL][B][NH][D];     // g[d] * Kq[d]
__device__ float g_sKg[LL][B][NH];       // sum_d g[d]*Kq[d]
__device__ float g_cb[LL][B][NH];        // sum_d beta[d]*Kq[d]
__device__ float g_sc[LL][B][NH][S];     // scores, then A = w*rstd (in place)
__device__ float g_c0[LL][B][NH];        // sum_s w*rstd*mean
__device__ float g_ctx[LL][B][NH][D];    // LN-folded context vectors
__device__ float g_of[LL][B][D];         // o_flat per layer
__device__ float g_attn[B][DC];          // concat attn outputs (after Wo+bo)
__device__ float g_p1[4][B][II];         // mlp1 partials (split over c)
__device__ float g_m1[B][II];            // gelu output
__device__ float g_p2[8][B][DC];         // mlp2 partials (split over i)
__device__ float g_h2[B][DC];            // residual sum

// ---------------- kernels ----------------

__global__ void k_idx(const int* __restrict__ ids) {
    int b = blockIdx.x, t = threadIdx.x;
    __shared__ int red[256];
    int best = -1;
    for (int s = t; s < S; s += 256)
        if (ids[b * S + s] != PADTOK) best = (s > best) ? s : best;
    red[t] = best; __syncthreads();
    for (int o = 128; o; o >>= 1) { if (t < o) red[t] = max(red[t], red[t + o]); __syncthreads(); }
    if (t == 0) g_idx[b] = (red[0] < 0) ? 0 : red[0];
}

// LN of the last-token row -> g_qh
__global__ __launch_bounds__(256) void k_qh(const float* __restrict__ hs0, const float* __restrict__ hs1,
                                            const float* __restrict__ ln_g, const float* __restrict__ ln_b) {
    int b = blockIdx.x, l = blockIdx.y, t = threadIdx.x;
    const float* hs = l ? hs1 : hs0;
    int ix = g_idx[b];
    const float* row = hs + ((size_t)b * S + ix) * D;
    __shared__ float red[256];
    float s = 0.f, s2 = 0.f;
    for (int d = t; d < D; d += 256) { float v = row[d]; s += v; s2 += v * v; }
    red[t] = s; __syncthreads();
    for (int o = 128; o; o >>= 1) { if (t < o) red[t] += red[t + o]; __syncthreads(); }
    float tot = red[0]; __syncthreads();
    red[t] = s2; __syncthreads();
    for (int o = 128; o; o >>= 1) { if (t < o) red[t] += red[t + o]; __syncthreads(); }
    float tot2 = red[0]; __syncthreads();
    float mean = tot * (1.f / D);
    float var  = tot2 * (1.f / D) - mean * mean;
    float rstd = rsqrtf(var + 1e-5f);
    for (int d = t; d < D; d += 256)
        g_qh[l][b][d] = (row[d] - mean) * rstd * ln_g[l * D + d] + ln_b[l * D + d];
}

// q[l][b][col] = qh[l][b][:] @ Wq[l][:,col]  (8 batches per block)
__global__ __launch_bounds__(256) void k_q(const float* __restrict__ Wq) {
    int l = blockIdx.y, t = threadIdx.x;
    int col = blockIdx.x * 256 + t;
    __shared__ float qs[8 * 512];
    float acc[8] = {0, 0, 0, 0, 0, 0, 0, 0};
    for (int c0 = 0; c0 < D; c0 += 512) {
        for (int e = t; e < 4096; e += 256) { int bb = e >> 9, dd = e & 511; qs[e] = g_qh[l][bb][c0 + dd]; }
        __syncthreads();
#pragma unroll 4
        for (int dd = 0; dd < 512; dd++) {
            float w = Wq[(size_t)l * D * D + (size_t)(c0 + dd) * D + col];
#pragma unroll
            for (int bb = 0; bb < 8; bb++) acc[bb] += qs[bb * 512 + dd] * w;
        }
        __syncthreads();
    }
    for (int bb = 0; bb < 8; bb++) g_q[l][bb][col] = acc[bb];
}

// Kg[l][b][h][dp] = g[dp] * sum_j q[l][b][h*128+j] * Wk[l][dp][h*128+j]; also sKg, cb
__global__ __launch_bounds__(256) void k_kq(const float* __restrict__ Wk,
                                            const float* __restrict__ ln_g, const float* __restrict__ ln_b) {
    int h = blockIdx.x, l = blockIdx.y, t = threadIdx.x;
    __shared__ float qs[8 * 128];
    __shared__ float red[256];
    for (int e = t; e < 1024; e += 256) { int bb = e >> 7, j = e & 127; qs[e] = g_q[l][bb][h * 128 + j]; }
    __syncthreads();
    float skp[8] = {0,0,0,0,0,0,0,0}, cbp[8] = {0,0,0,0,0,0,0,0};
    for (int i = 0; i < 8; i++) {
        int dp = i * 256 + t;
        float acc[8] = {0,0,0,0,0,0,0,0};
        const float4* wr = (const float4*)(Wk + (size_t)l * D * D + (size_t)dp * D + h * 128);
#pragma unroll 8
        for (int j4 = 0; j4 < 32; j4++) {
            float4 w = wr[j4];
#pragma unroll
            for (int bb = 0; bb < 8; bb++) {
                const float* qb = &qs[bb * 128 + j4 * 4];
                acc[bb] += qb[0] * w.x + qb[1] * w.y + qb[2] * w.z + qb[3] * w.w;
            }
        }
        float gd = ln_g[l * D + dp], bd = ln_b[l * D + dp];
#pragma unroll
        for (int bb = 0; bb < 8; bb++) {
            float kg = gd * acc[bb];
            g_Kg[l][bb][h][dp] = kg;
            skp[bb] += kg;
            cbp[bb] += bd * acc[bb];
        }
    }
    for (int bb = 0; bb < 8; bb++) {
        red[t] = skp[bb]; __syncthreads();
        for (int o = 128; o; o >>= 1) { if (t < o) red[t] += red[t + o]; __syncthreads(); }
        if (t == 0) g_sKg[l][bb][h] = red[0];
        __syncthreads();
        red[t] = cbp[bb]; __syncthreads();
        for (int o = 128; o; o >>= 1) { if (t < o) red[t] += red[t + o]; __syncthreads(); }
        if (t == 0) g_cb[l][bb][h] = red[0];
        __syncthreads();
    }
}

// scores pass: fused LN-stats + 16-head dot per row.  s-tile=256, d-chunk=32, 4s x 4h per thread.
__global__ __launch_bounds__(256) void k_scores(const float* __restrict__ hs0, const float* __restrict__ hs1) {
    int l = blockIdx.z, b = blockIdx.y;
    int s0 = blockIdx.x * 256;
    const float* hs = l ? hs1 : hs0;
    const int t = threadIdx.x;
    __shared__ float xs[256 * 36];
    __shared__ float kgs[16 * 36];
    __shared__ float smean[256], srstd[256];
    __shared__ float sskg[16], scb[16];
    if (t < 16) { sskg[t] = g_sKg[l][b][t]; scb[t] = g_cb[l][b][t]; }
    const float* rowp = hs + ((size_t)b * S + s0 + t) * D;
    float rs = 0.f, rs2 = 0.f;
    float acc[4][4];
#pragma unroll
    for (int j = 0; j < 4; j++)
#pragma unroll
        for (int k = 0; k < 4; k++) acc[j][k] = 0.f;
    int sg = t >> 2, hg = t & 3;
    for (int d0 = 0; d0 < D; d0 += 32) {
        const float4* src = (const float4*)(rowp + d0);
        float* xr = &xs[t * 36];
#pragma unroll
        for (int q = 0; q < 8; q++) {
            float4 v = src[q];
            rs  += v.x + v.y + v.z + v.w;
            rs2 += v.x * v.x + v.y * v.y + v.z * v.z + v.w * v.w;
            *((float4*)(xr + q * 4)) = v;
        }
        { int e = t * 2; int h = e >> 5, dd = e & 31;
          const float* kp = &g_Kg[l][b][h][d0 + dd];
          kgs[h * 36 + dd] = kp[0]; kgs[h * 36 + dd + 1] = kp[1]; }
        __syncthreads();
#pragma unroll 8
        for (int dd = 0; dd < 32; dd++) {
            float x0 = xs[sg * 36 + dd],        x1 = xs[(sg + 64) * 36 + dd];
            float x2 = xs[(sg + 128) * 36 + dd], x3 = xs[(sg + 192) * 36 + dd];
            float k0 = kgs[hg * 36 + dd],        k1 = kgs[(hg + 4) * 36 + dd];
            float k2 = kgs[(hg + 8) * 36 + dd],  k3 = kgs[(hg + 12) * 36 + dd];
            acc[0][0] += x0 * k0; acc[0][1] += x0 * k1; acc[0][2] += x0 * k2; acc[0][3] += x0 * k3;
            acc[1][0] += x1 * k0; acc[1][1] += x1 * k1; acc[1][2] += x1 * k2; acc[1][3] += x1 * k3;
            acc[2][0] += x2 * k0; acc[2][1] += x2 * k1; acc[2][2] += x2 * k2; acc[2][3] += x2 * k3;
            acc[3][0] += x3 * k0; acc[3][1] += x3 * k1; acc[3][2] += x3 * k2; acc[3][3] += x3 * k3;
        }
        __syncthreads();
    }
    float mean = rs * (1.f / D);
    float var  = rs2 * (1.f / D) - mean * mean;
    float rstd = rsqrtf(var + 1e-5f);
    g_mean[l][b][s0 + t] = mean;
    g_rstd[l][b][s0 + t] = rstd;
    smean[t] = mean; srstd[t] = rstd;
    __syncthreads();
#pragma unroll
    for (int j = 0; j < 4; j++) {
        int s = sg + j * 64;
        float m = smean[s], r = srstd[s];
#pragma unroll
        for (int k = 0; k < 4; k++) {
            int h = hg + k * 4;
            g_sc[l][b][h][s0 + s] = r * (acc[j][k] - m * sskg[h]) + scb[h];
        }
    }
}

// softmax over S, then write A = w*rstd in place and c0 = sum w*rstd*mean
__global__ __launch_bounds__(256) void k_softmax() {
    int h = blockIdx.x, b = blockIdx.y, l = blockIdx.z, t = threadIdx.x;
    float* sc = &g_sc[l][b][h][0];
    __shared__ float buf[S];
    __shared__ float red[256];
    float mx = -1e30f;
    for (int s = t; s < S; s += 256) { float v = sc[s]; buf[s] = v; mx = fmaxf(mx, v); }
    red[t] = mx; __syncthreads();
    for (int o = 128; o; o >>= 1) { if (t < o) red[t] = fmaxf(red[t], red[t + o]); __syncthreads(); }
    mx = red[0]; __syncthreads();
    float sum = 0.f;
    for (int s = t; s < S; s += 256) { float e = expf(buf[s] - mx); buf[s] = e; sum += e; }
    red[t] = sum; __syncthreads();
    for (int o = 128; o; o >>= 1) { if (t < o) red[t] += red[t + o]; __syncthreads(); }
    float inv = 1.f / red[0]; __syncthreads();
    float c0 = 0.f;
    for (int s = t; s < S; s += 256) {
        float w = buf[s] * inv;
        float r = g_rstd[l][b][s], m = g_mean[l][b][s];
        sc[s] = w * r;
        c0 += w * r * m;
    }
    red[t] = c0; __syncthreads();
    for (int o = 128; o; o >>= 1) { if (t < o) red[t] += red[t + o]; __syncthreads(); }
    if (t == 0) g_c0[l][b][h] = red[0];
}

// ctx pass: ctx[h][d] = g[d]*(sum_s A[h][s]*x[s][d] - c0[h]) + beta[d].  d-tile=256, s-chunk=32.
__global__ __launch_bounds__(256) void k_ctx(const float* __restrict__ hs0, const float* __restrict__ hs1,
                                             const float* __restrict__ ln_g, const float* __restrict__ ln_b) {
    int l = blockIdx.z, b = blockIdx.y;
    int dt0 = blockIdx.x * 256;
    const float* hs = l ? hs1 : hs0;
    int t = threadIdx.x;
    __shared__ float xt[32 * 256];
    __shared__ float At[16 * 36];
    __shared__ float sc0[16];
    if (t < 16) sc0[t] = g_c0[l][b][t];
    int dg = t >> 2, hg = t & 3;
    float acc[4][4];
#pragma unroll
    for (int j = 0; j < 4; j++)
#pragma unroll
        for (int k = 0; k < 4; k++) acc[j][k] = 0.f;
    for (int s0 = 0; s0 < S; s0 += 32) {
#pragma unroll
        for (int w = 0; w < 8; w++) {
            int e4 = t + w * 256;
            int row = e4 >> 6, c4 = e4 & 63;
            float4 v = *(const float4*)(hs + ((size_t)b * S + s0 + row) * D + dt0 + c4 * 4);
            *(float4*)&xt[row * 256 + c4 * 4] = v;
        }
        { int e = t * 2; int h = e >> 5, ss = e & 31;
          const float* ap = &g_sc[l][b][h][s0 + ss];
          At[h * 36 + ss] = ap[0]; At[h * 36 + ss + 1] = ap[1]; }
        __syncthreads();
#pragma unroll 8
        for (int ss = 0; ss < 32; ss++) {
            float a0 = At[hg * 36 + ss],        a1 = At[(hg + 4) * 36 + ss];
            float a2 = At[(hg + 8) * 36 + ss],  a3 = At[(hg + 12) * 36 + ss];
            float x0 = xt[ss * 256 + dg],        x1 = xt[ss * 256 + dg + 64];
            float x2 = xt[ss * 256 + dg + 128],  x3 = xt[ss * 256 + dg + 192];
            acc[0][0] += x0 * a0; acc[0][1] += x0 * a1; acc[0][2] += x0 * a2; acc[0][3] += x0 * a3;
            acc[1][0] += x1 * a0; acc[1][1] += x1 * a1; acc[1][2] += x1 * a2; acc[1][3] += x1 * a3;
            acc[2][0] += x2 * a0; acc[2][1] += x2 * a1; acc[2][2] += x2 * a2; acc[2][3] += x2 * a3;
            acc[3][0] += x3 * a0; acc[3][1] += x3 * a1; acc[3][2] += x3 * a2; acc[3][3] += x3 * a3;
        }
        __syncthreads();
    }
#pragma unroll
    for (int j = 0; j < 4; j++) {
        int d = dt0 + dg + j * 64;
        float gd = ln_g[l * D + d], bd = ln_b[l * D + d];
#pragma unroll
        for (int k = 0; k < 4; k++) {
            int h = hg + k * 4;
            g_ctx[l][b][h][d] = gd * (acc[j][k] - sc0[h]) + bd;
        }
    }
}

// o_flat[l][b][h*128+d] = sum_dp ctx[l][b][h][dp] * Wv[l][dp][h*128+d]
__global__ __launch_bounds__(128) void k_ov(const float* __restrict__ Wv) {
    int h = blockIdx.x, l = blockIdx.y, t = threadIdx.x;
    __shared__ float cs[8 * 1024];
    float acc[8] = {0,0,0,0,0,0,0,0};
    for (int c0 = 0; c0 < D; c0 += 1024) {
        for (int e = t; e < 8192; e += 128) { int bb = e >> 10, dd = e & 1023; cs[e] = g_ctx[l][bb][h][c0 + dd]; }
        __syncthreads();
#pragma unroll 4
        for (int dp = 0; dp < 1024; dp++) {
            float w = Wv[(size_t)l * D * D + (size_t)(c0 + dp) * D + h * 128 + t];
#pragma unroll
            for (int bb = 0; bb < 8; bb++) acc[bb] += cs[bb * 1024 + dp] * w;
        }
        __syncthreads();
    }
    for (int bb = 0; bb < 8; bb++) g_of[l][bb][h * 128 + t] = acc[bb];
}

// attn[b][l*D+col] = o_flat[l][b][:] @ Wo[l][:,col] + bo[l][col]
__global__ __launch_bounds__(256) void k_wo(const float* __restrict__ Wo, const float* __restrict__ bo) {
    int l = blockIdx.y, t = threadIdx.x;
    int col = blockIdx.x * 256 + t;
    __shared__ float os[8 * 512];
    float acc[8];
    float bv = bo[l * D + col];
    for (int bb = 0; bb < 8; bb++) acc[bb] = bv;
    for (int e0 = 0; e0 < D; e0 += 512) {
        for (int e = t; e < 4096; e += 256) { int bb = e >> 9, dd = e & 511; os[e] = g_of[l][bb][e0 + dd]; }
        __syncthreads();
#pragma unroll 4
        for (int dd = 0; dd < 512; dd++) {
            float w = Wo[(size_t)l * D * D + (size_t)(e0 + dd) * D + col];
#pragma unroll
            for (int bb = 0; bb < 8; bb++) acc[bb] += os[bb * 512 + dd] * w;
        }
        __syncthreads();
    }
    for (int bb = 0; bb < 8; bb++) g_attn[bb][l * D + col] = acc[bb];
}

// mlp1 partial: p1[cs][b][i] = sum_{c in cs-range} attn[b][c]*W1[c][i]
__global__ __launch_bounds__(256) void k_mlp1(const float* __restrict__ W1) {
    int it = blockIdx.x;   // 0..31 (512 cols each)
    int cs = blockIdx.y;   // 0..3  (1024 c each)
    int t = threadIdx.x;
    int col0 = it * 512 + t;
    int cbase = cs * 1024;
    __shared__ float as[8 * 1024];
    for (int e = t; e < 8192; e += 256) { int bb = e >> 10, cc = e & 1023; as[e] = g_attn[bb][cbase + cc]; }
    __syncthreads();
    float a0[8] = {0,0,0,0,0,0,0,0}, a1[8] = {0,0,0,0,0,0,0,0};
#pragma unroll 4
    for (int cc = 0; cc < 1024; cc++) {
        const float* wr = W1 + (size_t)(cbase + cc) * II + col0;
        float w0 = wr[0], w1 = wr[256];
#pragma unroll
        for (int bb = 0; bb < 8; bb++) {
            float av = as[bb * 1024 + cc];
            a0[bb] += av * w0; a1[bb] += av * w1;
        }
    }
    for (int bb = 0; bb < 8; bb++) { g_p1[cs][bb][col0] = a0[bb]; g_p1[cs][bb][col0 + 256] = a1[bb]; }
}

__global__ void k_gelu(const float* __restrict__ b1) {
    int e = blockIdx.x * 256 + threadIdx.x;
    int bb = e / II, i = e % II;
    float x = g_p1[0][bb][i] + g_p1[1][bb][i] + g_p1[2][bb][i] + g_p1[3][bb][i] + b1[i];
    g_m1[bb][i] = 0.5f * x * (1.0f + erff(x * 0.70710678118654752f));
}

// mlp2 partial: p2[isp][b][c] = sum_{i in isp-range} m1[b][i]*W2[i][c]
__global__ __launch_bounds__(256) void k_mlp2(const float* __restrict__ W2) {
    int ct = blockIdx.x;   // 0..15
    int isp = blockIdx.y;  // 0..7
    int t = threadIdx.x;
    int col = ct * 256 + t;
    __shared__ float ms[8 * 1024];
    float acc[8] = {0,0,0,0,0,0,0,0};
    for (int sub = 0; sub < 2; sub++) {
        int ibase = isp * 2048 + sub * 1024;
        for (int e = t; e < 8192; e += 256) { int bb = e >> 10, ii = e & 1023; ms[e] = g_m1[bb][ibase + ii]; }
        __syncthreads();
#pragma unroll 4
        for (int ii = 0; ii < 1024; ii++) {
            float w = W2[(size_t)(ibase + ii) * DC + col];
#pragma unroll
            for (int bb = 0; bb < 8; bb++) acc[bb] += ms[bb * 1024 + ii] * w;
        }
        __syncthreads();
    }
    for (int bb = 0; bb < 8; bb++) g_p2[isp][bb][col] = acc[bb];
}

__global__ void k_h2(const float* __restrict__ b2) {
    int e = blockIdx.x * 256 + threadIdx.x;
    int bb = e / DC, c = e % DC;
    float s = g_attn[bb][c] + b2[c];
#pragma unroll
    for (int i = 0; i < 8; i++) s += g_p2[i][bb][c];
    g_h2[bb][c] = s;
}

__global__ __launch_bounds__(256) void k_logits(const float* __restrict__ Wl, const float* __restrict__ bl,
                                                float* __restrict__ out) {
    int b = blockIdx.x >> 1, j = blockIdx.x & 1, t = threadIdx.x;
    __shared__ float red[256];
    float s = 0.f;
    for (int c = t; c < DC; c += 256) s += g_h2[b][c] * Wl[c * 2 + j];
    red[t] = s; __syncthreads();
    for (int o = 128; o; o >>= 1) { if (t < o) red[t] += red[t + o]; __syncthreads(); }
    if (t == 0) out[b * 2 + j] = red[0] + bl[j];
}

// ---------------- launch ----------------
extern "C" void kernel_launch(void* const* d_in, const int* in_sizes, int n_in,
                              void* d_out, int out_size) {
    const float* hs0  = (const float*)d_in[0];
    const float* hs1  = (const float*)d_in[1];
    const int*   ids  = (const int*)  d_in[2];
    const float* ln_g = (const float*)d_in[3];
    const float* ln_b = (const float*)d_in[4];
    const float* Wq   = (const float*)d_in[5];
    const float* Wk   = (const float*)d_in[6];
    const float* Wv   = (const float*)d_in[7];
    const float* Wo   = (const float*)d_in[8];
    const float* bo   = (const float*)d_in[9];
    const float* W1   = (const float*)d_in[10];
    const float* b1   = (const float*)d_in[11];
    const float* W2   = (const float*)d_in[12];
    const float* b2   = (const float*)d_in[13];
    const float* Wl   = (const float*)d_in[14];
    const float* bl   = (const float*)d_in[15];
    float* out = (float*)d_out;

    k_idx<<<B, 256>>>(ids);
    k_qh<<<dim3(B, LL), 256>>>(hs0, hs1, ln_g, ln_b);
    k_q<<<dim3(D / 256, LL), 256>>>(Wq);
    k_kq<<<dim3(NH, LL), 256>>>(Wk, ln_g, ln_b);
    k_scores<<<dim3(S / 256, B, LL), 256>>>(hs0, hs1);
    k_softmax<<<dim3(NH, B, LL), 256>>>();
    k_ctx<<<dim3(D / 256, B, LL), 256>>>(hs0, hs1, ln_g, ln_b);
    k_ov<<<dim3(NH, LL), 128>>>(Wv);
    k_wo<<<dim3(D / 256, LL), 256>>>(Wo, bo);
    k_mlp1<<<dim3(32, 4), 256>>>(W1);
    k_gelu<<<(B * II) / 256, 256>>>(b1);
    k_mlp2<<<dim3(16, 8), 256>>>(W2);
    k_h2<<<(B * DC) / 256, 256>>>(b2);
    k_logits<<<B * 2, 256>>>(Wl, bl, out);
}

// round 9
// speedup vs baseline: 3.0298x; 3.0298x over previous
#include <cuda_runtime.h>
#include <math.h>

#define LL 2
#define B 8
#define S 2048
#define D 2048
#define NH 16
#define HD 128
#define DC 4096
#define II 16384
#define PADTOK 50257

// ---------------- scratch ----------------
__device__ int   g_idx[B];
__device__ float g_mean[LL][B][S];
__device__ float g_rstd[LL][B][S];
__device__ float g_qh[LL][B][D];
__device__ float g_qp[8][LL][B][D];      // q partials (csplit)
__device__ float g_q[LL][B][D];
__device__ float g_Kg[LL][B][NH][D];     // g[d] * Kq[d]
__device__ float g_skp[8][LL][B][NH];    // partial sum g*Kq
__device__ float g_cbp[8][LL][B][NH];    // partial sum beta*Kq
__device__ float g_sKg[LL][B][NH];
__device__ float g_cb[LL][B][NH];
__device__ float g_sc[LL][B][NH][S];     // scores, then A = w*rstd in place
__device__ float g_c0[LL][B][NH];
__device__ float g_ctx[LL][B][NH][D];
__device__ float g_ofp[8][LL][B][D];     // o_flat partials (dp split)
__device__ float g_of[LL][B][D];
__device__ float g_wop[8][LL][B][D];     // wo partials (e split)
__device__ float g_attn[B][DC];
__device__ float g_p1[16][B][II];        // mlp1 partials (16 x 256-row chunks)
__device__ float g_m1[B][II];
__device__ float g_p2[64][B][DC];        // mlp2 partials (64 x 256-row chunks)
__device__ float g_h2[B][DC];

// ---------------- small kernels ----------------

__global__ void k_idx(const int* __restrict__ ids) {
    int b = blockIdx.x, t = threadIdx.x;
    __shared__ int red[256];
    int best = -1;
    for (int s = t; s < S; s += 256)
        if (ids[b * S + s] != PADTOK) best = (s > best) ? s : best;
    red[t] = best; __syncthreads();
    for (int o = 128; o; o >>= 1) { if (t < o) red[t] = max(red[t], red[t + o]); __syncthreads(); }
    if (t == 0) g_idx[b] = (red[0] < 0) ? 0 : red[0];
}

__global__ __launch_bounds__(256) void k_qh(const float* __restrict__ hs0, const float* __restrict__ hs1,
                                            const float* __restrict__ ln_g, const float* __restrict__ ln_b) {
    int b = blockIdx.x, l = blockIdx.y, t = threadIdx.x;
    const float* hs = l ? hs1 : hs0;
    int ix = g_idx[b];
    const float* row = hs + ((size_t)b * S + ix) * D;
    __shared__ float red[256];
    float s = 0.f, s2 = 0.f;
    for (int d = t; d < D; d += 256) { float v = row[d]; s += v; s2 += v * v; }
    red[t] = s; __syncthreads();
    for (int o = 128; o; o >>= 1) { if (t < o) red[t] += red[t + o]; __syncthreads(); }
    float tot = red[0]; __syncthreads();
    red[t] = s2; __syncthreads();
    for (int o = 128; o; o >>= 1) { if (t < o) red[t] += red[t + o]; __syncthreads(); }
    float tot2 = red[0]; __syncthreads();
    float mean = tot * (1.f / D);
    float var  = tot2 * (1.f / D) - mean * mean;
    float rstd = rsqrtf(var + 1e-5f);
    for (int d = t; d < D; d += 256)
        g_qh[l][b][d] = (row[d] - mean) * rstd * ln_g[l * D + d] + ln_b[l * D + d];
}

// ---------------- q projection (split over c) ----------------
__global__ __launch_bounds__(256) void k_qp(const float* __restrict__ Wq) {
    int ct = blockIdx.x, cs = blockIdx.y, l = blockIdx.z, t = threadIdx.x;
    int col = ct * 256 + t;
    int c0 = cs * 256;
    __shared__ float qs[8 * 256];
    for (int e = t; e < 2048; e += 256) { int bb = e >> 8, cc = e & 255; qs[e] = g_qh[l][bb][c0 + cc]; }
    __syncthreads();
    float acc[8] = {0,0,0,0,0,0,0,0};
#pragma unroll 4
    for (int cc = 0; cc < 256; cc++) {
        float w = Wq[(size_t)l * D * D + (size_t)(c0 + cc) * D + col];
#pragma unroll
        for (int bb = 0; bb < 8; bb++) acc[bb] += qs[bb * 256 + cc] * w;
    }
    for (int bb = 0; bb < 8; bb++) g_qp[cs][l][bb][col] = acc[bb];
}

__global__ void k_qred() {
    int idx = blockIdx.x * 256 + threadIdx.x;  // over LL*B*D = 32768
    int l = idx >> 14, r = idx & 16383, b = r >> 11, col = r & 2047;
    float s = 0.f;
#pragma unroll
    for (int p = 0; p < 8; p++) s += g_qp[p][l][b][col];
    g_q[l][b][col] = s;
}

// ---------------- Kq (split over dp) ----------------
__global__ __launch_bounds__(256) void k_kqp(const float* __restrict__ Wk,
                                             const float* __restrict__ ln_g, const float* __restrict__ ln_b) {
    int h = blockIdx.x, p = blockIdx.y, l = blockIdx.z, t = threadIdx.x;
    int dp = p * 256 + t;
    __shared__ __align__(16) float qs[8 * 128];
    __shared__ float red[256];
    for (int e = t; e < 1024; e += 256) { int bb = e >> 7, j = e & 127; qs[e] = g_q[l][bb][h * 128 + j]; }
    __syncthreads();
    float acc[8] = {0,0,0,0,0,0,0,0};
    const float4* wr = (const float4*)(Wk + (size_t)l * D * D + (size_t)dp * D + h * 128);
#pragma unroll 8
    for (int j4 = 0; j4 < 32; j4++) {
        float4 w = wr[j4];
#pragma unroll
        for (int bb = 0; bb < 8; bb++) {
            const float* qb = &qs[bb * 128 + j4 * 4];
            acc[bb] += qb[0] * w.x + qb[1] * w.y + qb[2] * w.z + qb[3] * w.w;
        }
    }
    float gd = ln_g[l * D + dp], bd = ln_b[l * D + dp];
    for (int bb = 0; bb < 8; bb++) {
        float kg = gd * acc[bb];
        g_Kg[l][bb][h][dp] = kg;
        red[t] = kg; __syncthreads();
        for (int o = 128; o; o >>= 1) { if (t < o) red[t] += red[t + o]; __syncthreads(); }
        if (t == 0) g_skp[p][l][bb][h] = red[0];
        __syncthreads();
        red[t] = bd * acc[bb]; __syncthreads();
        for (int o = 128; o; o >>= 1) { if (t < o) red[t] += red[t + o]; __syncthreads(); }
        if (t == 0) g_cbp[p][l][bb][h] = red[0];
        __syncthreads();
    }
}

__global__ void k_kqred() {
    int t = threadIdx.x;  // 256 = LL*B*NH
    int l = t >> 7, b = (t >> 4) & 7, h = t & 15;
    float s = 0.f, c = 0.f;
#pragma unroll
    for (int p = 0; p < 8; p++) { s += g_skp[p][l][b][h]; c += g_cbp[p][l][b][h]; }
    g_sKg[l][b][h] = s;
    g_cb[l][b][h] = c;
}

// ---------------- scores pass (fused LN stats), float4 inner ----------------
__global__ __launch_bounds__(256, 1) void k_scores(const float* __restrict__ hs0, const float* __restrict__ hs1) {
    int l = blockIdx.z, b = blockIdx.y;
    int s0 = blockIdx.x * 256;
    const float* hs = l ? hs1 : hs0;
    const int t = threadIdx.x;
    __shared__ __align__(16) float xs[256 * 36];
    __shared__ __align__(16) float kgs[16 * 36];
    __shared__ float smean[256], srstd[256];
    __shared__ float sskg[16], scb[16];
    if (t < 16) { sskg[t] = g_sKg[l][b][t]; scb[t] = g_cb[l][b][t]; }
    const float* rowp = hs + ((size_t)b * S + s0 + t) * D;
    float rs = 0.f, rs2 = 0.f;
    float acc[4][4];
#pragma unroll
    for (int j = 0; j < 4; j++)
#pragma unroll
        for (int k = 0; k < 4; k++) acc[j][k] = 0.f;
    int sg = t >> 2, hg = t & 3;
    for (int d0 = 0; d0 < D; d0 += 32) {
        const float4* src = (const float4*)(rowp + d0);
        float* xr = &xs[t * 36];
#pragma unroll
        for (int q = 0; q < 8; q++) {
            float4 v = src[q];
            rs  += v.x + v.y + v.z + v.w;
            rs2 += v.x * v.x + v.y * v.y + v.z * v.z + v.w * v.w;
            *((float4*)(xr + q * 4)) = v;
        }
        { int e = t * 2; int h = e >> 5, dd = e & 31;
          const float* kp = &g_Kg[l][b][h][d0 + dd];
          kgs[h * 36 + dd] = kp[0]; kgs[h * 36 + dd + 1] = kp[1]; }
        __syncthreads();
#pragma unroll
        for (int dd = 0; dd < 32; dd += 4) {
            float4 x0 = *(const float4*)&xs[sg * 36 + dd];
            float4 x1 = *(const float4*)&xs[(sg + 64) * 36 + dd];
            float4 x2 = *(const float4*)&xs[(sg + 128) * 36 + dd];
            float4 x3 = *(const float4*)&xs[(sg + 192) * 36 + dd];
            float4 k0 = *(const float4*)&kgs[hg * 36 + dd];
            float4 k1 = *(const float4*)&kgs[(hg + 4) * 36 + dd];
            float4 k2 = *(const float4*)&kgs[(hg + 8) * 36 + dd];
            float4 k3 = *(const float4*)&kgs[(hg + 12) * 36 + dd];
#define DOT4(A, X, K) A += X.x*K.x; A += X.y*K.y; A += X.z*K.z; A += X.w*K.w;
            DOT4(acc[0][0], x0, k0) DOT4(acc[0][1], x0, k1) DOT4(acc[0][2], x0, k2) DOT4(acc[0][3], x0, k3)
            DOT4(acc[1][0], x1, k0) DOT4(acc[1][1], x1, k1) DOT4(acc[1][2], x1, k2) DOT4(acc[1][3], x1, k3)
            DOT4(acc[2][0], x2, k0) DOT4(acc[2][1], x2, k1) DOT4(acc[2][2], x2, k2) DOT4(acc[2][3], x2, k3)
            DOT4(acc[3][0], x3, k0) DOT4(acc[3][1], x3, k1) DOT4(acc[3][2], x3, k2) DOT4(acc[3][3], x3, k3)
#undef DOT4
        }
        __syncthreads();
    }
    float mean = rs * (1.f / D);
    float var  = rs2 * (1.f / D) - mean * mean;
    float rstd = rsqrtf(var + 1e-5f);
    g_mean[l][b][s0 + t] = mean;
    g_rstd[l][b][s0 + t] = rstd;
    smean[t] = mean; srstd[t] = rstd;
    __syncthreads();
#pragma unroll
    for (int j = 0; j < 4; j++) {
        int s = sg + j * 64;
        float m = smean[s], r = srstd[s];
#pragma unroll
        for (int k = 0; k < 4; k++) {
            int h = hg + k * 4;
            g_sc[l][b][h][s0 + s] = r * (acc[j][k] - m * sskg[h]) + scb[h];
        }
    }
}

// ---------------- softmax; A = w*rstd in place; c0 ----------------
__global__ __launch_bounds__(256) void k_softmax() {
    int h = blockIdx.x, b = blockIdx.y, l = blockIdx.z, t = threadIdx.x;
    float* sc = &g_sc[l][b][h][0];
    __shared__ float buf[S];
    __shared__ float red[256];
    float mx = -1e30f;
    for (int s = t; s < S; s += 256) { float v = sc[s]; buf[s] = v; mx = fmaxf(mx, v); }
    red[t] = mx; __syncthreads();
    for (int o = 128; o; o >>= 1) { if (t < o) red[t] = fmaxf(red[t], red[t + o]); __syncthreads(); }
    mx = red[0]; __syncthreads();
    float sum = 0.f;
    for (int s = t; s < S; s += 256) { float e = expf(buf[s] - mx); buf[s] = e; sum += e; }
    red[t] = sum; __syncthreads();
    for (int o = 128; o; o >>= 1) { if (t < o) red[t] += red[t + o]; __syncthreads(); }
    float inv = 1.f / red[0]; __syncthreads();
    float c0 = 0.f;
    for (int s = t; s < S; s += 256) {
        float w = buf[s] * inv;
        float r = g_rstd[l][b][s], m = g_mean[l][b][s];
        sc[s] = w * r;
        c0 += w * r * m;
    }
    red[t] = c0; __syncthreads();
    for (int o = 128; o; o >>= 1) { if (t < o) red[t] += red[t + o]; __syncthreads(); }
    if (t == 0) g_c0[l][b][h] = red[0];
}

// ---------------- ctx pass, float4 inner ----------------
__global__ __launch_bounds__(256, 1) void k_ctx(const float* __restrict__ hs0, const float* __restrict__ hs1,
                                                const float* __restrict__ ln_g, const float* __restrict__ ln_b) {
    int l = blockIdx.z, b = blockIdx.y;
    int dt0 = blockIdx.x * 256;
    const float* hs = l ? hs1 : hs0;
    int t = threadIdx.x;
    __shared__ __align__(16) float xt[32 * 256];
    __shared__ __align__(16) float At[16 * 36];
    __shared__ float sc0[16];
    if (t < 16) sc0[t] = g_c0[l][b][t];
    int dgrp = t & 63, hgrp = t >> 6;   // d = dt0 + dgrp*4 .. +3 ; heads hgrp + 4k
    float4 acc[4];
#pragma unroll
    for (int k = 0; k < 4; k++) acc[k] = make_float4(0.f, 0.f, 0.f, 0.f);
    for (int s0 = 0; s0 < S; s0 += 32) {
#pragma unroll
        for (int w = 0; w < 8; w++) {
            int e4 = t + w * 256;
            int row = e4 >> 6, c4 = e4 & 63;
            float4 v = *(const float4*)(hs + ((size_t)b * S + s0 + row) * D + dt0 + c4 * 4);
            *(float4*)&xt[row * 256 + c4 * 4] = v;
        }
        { int e = t * 2; int h = e >> 5, ss = e & 31;
          const float* ap = &g_sc[l][b][h][s0 + ss];
          At[h * 36 + ss] = ap[0]; At[h * 36 + ss + 1] = ap[1]; }
        __syncthreads();
#pragma unroll
        for (int ss = 0; ss < 32; ss += 4) {
            float4 xA = *(const float4*)&xt[(ss + 0) * 256 + dgrp * 4];
            float4 xB = *(const float4*)&xt[(ss + 1) * 256 + dgrp * 4];
            float4 xC = *(const float4*)&xt[(ss + 2) * 256 + dgrp * 4];
            float4 xD = *(const float4*)&xt[(ss + 3) * 256 + dgrp * 4];
#pragma unroll
            for (int k = 0; k < 4; k++) {
                float4 a = *(const float4*)&At[(hgrp + 4 * k) * 36 + ss];
                acc[k].x += xA.x * a.x; acc[k].x += xB.x * a.y; acc[k].x += xC.x * a.z; acc[k].x += xD.x * a.w;
                acc[k].y += xA.y * a.x; acc[k].y += xB.y * a.y; acc[k].y += xC.y * a.z; acc[k].y += xD.y * a.w;
                acc[k].z += xA.z * a.x; acc[k].z += xB.z * a.y; acc[k].z += xC.z * a.z; acc[k].z += xD.z * a.w;
                acc[k].w += xA.w * a.x; acc[k].w += xB.w * a.y; acc[k].w += xC.w * a.z; acc[k].w += xD.w * a.w;
            }
        }
        __syncthreads();
    }
    int d = dt0 + dgrp * 4;
    float4 gd = *(const float4*)&ln_g[l * D + d];
    float4 bd = *(const float4*)&ln_b[l * D + d];
#pragma unroll
    for (int k = 0; k < 4; k++) {
        int h = hgrp + 4 * k;
        float c0h = sc0[h];
        float4 o;
        o.x = gd.x * (acc[k].x - c0h) + bd.x;
        o.y = gd.y * (acc[k].y - c0h) + bd.y;
        o.z = gd.z * (acc[k].z - c0h) + bd.z;
        o.w = gd.w * (acc[k].w - c0h) + bd.w;
        *(float4*)&g_ctx[l][b][h][d] = o;
    }
}

// ---------------- V projection (split over dp) ----------------
__global__ __launch_bounds__(128) void k_ovp(const float* __restrict__ Wv) {
    int h = blockIdx.x, ds = blockIdx.y, l = blockIdx.z, t = threadIdx.x;
    int dp0 = ds * 256;
    __shared__ float cs_[8 * 256];
    for (int e = t; e < 2048; e += 128) { int bb = e >> 8, dd = e & 255; cs_[e] = g_ctx[l][bb][h][dp0 + dd]; }
    __syncthreads();
    float acc[8] = {0,0,0,0,0,0,0,0};
#pragma unroll 4
    for (int dp = 0; dp < 256; dp++) {
        float w = Wv[(size_t)l * D * D + (size_t)(dp0 + dp) * D + h * 128 + t];
#pragma unroll
        for (int bb = 0; bb < 8; bb++) acc[bb] += cs_[bb * 256 + dp] * w;
    }
    for (int bb = 0; bb < 8; bb++) g_ofp[ds][l][bb][h * 128 + t] = acc[bb];
}

__global__ void k_ovred() {
    int idx = blockIdx.x * 256 + threadIdx.x;  // LL*B*D
    int l = idx >> 14, r = idx & 16383, b = r >> 11, col = r & 2047;
    float s = 0.f;
#pragma unroll
    for (int p = 0; p < 8; p++) s += g_ofp[p][l][b][col];
    g_of[l][b][col] = s;
}

// ---------------- Wo projection (split over e) ----------------
__global__ __launch_bounds__(256) void k_wop(const float* __restrict__ Wo) {
    int ct = blockIdx.x, es = blockIdx.y, l = blockIdx.z, t = threadIdx.x;
    int col = ct * 256 + t;
    int e0 = es * 256;
    __shared__ float os[8 * 256];
    for (int e = t; e < 2048; e += 256) { int bb = e >> 8, ee = e & 255; os[e] = g_of[l][bb][e0 + ee]; }
    __syncthreads();
    float acc[8] = {0,0,0,0,0,0,0,0};
#pragma unroll 4
    for (int ee = 0; ee < 256; ee++) {
        float w = Wo[(size_t)l * D * D + (size_t)(e0 + ee) * D + col];
#pragma unroll
        for (int bb = 0; bb < 8; bb++) acc[bb] += os[bb * 256 + ee] * w;
    }
    for (int bb = 0; bb < 8; bb++) g_wop[es][l][bb][col] = acc[bb];
}

__global__ void k_wored(const float* __restrict__ bo) {
    int idx = blockIdx.x * 256 + threadIdx.x;  // LL*B*D
    int l = idx >> 14, r = idx & 16383, b = r >> 11, col = r & 2047;
    float s = bo[l * D + col];
#pragma unroll
    for (int p = 0; p < 8; p++) s += g_wop[p][l][b][col];
    g_attn[b][l * D + col] = s;
}

// ---------------- MLP (256 CTAs each: no wave quantization on 148 SMs) ----------------
__global__ __launch_bounds__(256) void k_mlp1(const float* __restrict__ W1) {
    int it = blockIdx.x;   // 0..15 -> 256 float4-cols each
    int cs = blockIdx.y;   // 0..15 -> 256 rows each
    int t = threadIdx.x;
    int col4 = it * 256 + t;
    int cbase = cs * 256;
    __shared__ float as[8 * 256];
    for (int e = t; e < 2048; e += 256) { int bb = e >> 8, cc = e & 255; as[e] = g_attn[bb][cbase + cc]; }
    __syncthreads();
    float4 acc[8];
#pragma unroll
    for (int bb = 0; bb < 8; bb++) acc[bb] = make_float4(0.f, 0.f, 0.f, 0.f);
#pragma unroll 4
    for (int cc = 0; cc < 256; cc++) {
        float4 w = *(const float4*)(W1 + (size_t)(cbase + cc) * II + col4 * 4);
#pragma unroll
        for (int bb = 0; bb < 8; bb++) {
            float av = as[bb * 256 + cc];
            acc[bb].x += av * w.x; acc[bb].y += av * w.y; acc[bb].z += av * w.z; acc[bb].w += av * w.w;
        }
    }
    for (int bb = 0; bb < 8; bb++) *(float4*)&g_p1[cs][bb][col4 * 4] = acc[bb];
}

__global__ void k_gelu(const float* __restrict__ b1) {
    int e = blockIdx.x * 256 + threadIdx.x;
    int bb = e / II, i = e % II;
    float x = b1[i];
#pragma unroll
    for (int p = 0; p < 16; p++) x += g_p1[p][bb][i];
    g_m1[bb][i] = 0.5f * x * (1.0f + erff(x * 0.70710678118654752f));
}

__global__ __launch_bounds__(256) void k_mlp2(const float* __restrict__ W2) {
    int ct = blockIdx.x;   // 0..3 -> 256 float4-cols each (DC/4 = 1024)
    int isp = blockIdx.y;  // 0..63 -> 256 rows each
    int t = threadIdx.x;
    int col4 = ct * 256 + t;
    int ibase = isp * 256;
    __shared__ float ms[8 * 256];
    for (int e = t; e < 2048; e += 256) { int bb = e >> 8, ii = e & 255; ms[e] = g_m1[bb][ibase + ii]; }
    __syncthreads();
    float4 acc[8];
#pragma unroll
    for (int bb = 0; bb < 8; bb++) acc[bb] = make_float4(0.f, 0.f, 0.f, 0.f);
#pragma unroll 4
    for (int ii = 0; ii < 256; ii++) {
        float4 w = *(const float4*)(W2 + (size_t)(ibase + ii) * DC + col4 * 4);
#pragma unroll
        for (int bb = 0; bb < 8; bb++) {
            float mv = ms[bb * 256 + ii];
            acc[bb].x += mv * w.x; acc[bb].y += mv * w.y; acc[bb].z += mv * w.z; acc[bb].w += mv * w.w;
        }
    }
    for (int bb = 0; bb < 8; bb++) *(float4*)&g_p2[isp][bb][col4 * 4] = acc[bb];
}

__global__ void k_h2(const float* __restrict__ b2) {
    int e = blockIdx.x * 256 + threadIdx.x;
    int bb = e / DC, c = e % DC;
    float s = g_attn[bb][c] + b2[c];
#pragma unroll
    for (int i = 0; i < 64; i++) s += g_p2[i][bb][c];
    g_h2[bb][c] = s;
}

__global__ __launch_bounds__(256) void k_logits(const float* __restrict__ Wl, const float* __restrict__ bl,
                                                float* __restrict__ out) {
    int b = blockIdx.x >> 1, j = blockIdx.x & 1, t = threadIdx.x;
    __shared__ float red[256];
    float s = 0.f;
    for (int c = t; c < DC; c += 256) s += g_h2[b][c] * Wl[c * 2 + j];
    red[t] = s; __syncthreads();
    for (int o = 128; o; o >>= 1) { if (t < o) red[t] += red[t + o]; __syncthreads(); }
    if (t == 0) out[b * 2 + j] = red[0] + bl[j];
}

// ---------------- launch ----------------
extern "C" void kernel_launch(void* const* d_in, const int* in_sizes, int n_in,
                              void* d_out, int out_size) {
    const float* hs0  = (const float*)d_in[0];
    const float* hs1  = (const float*)d_in[1];
    const int*   ids  = (const int*)  d_in[2];
    const float* ln_g = (const float*)d_in[3];
    const float* ln_b = (const float*)d_in[4];
    const float* Wq   = (const float*)d_in[5];
    const float* Wk   = (const float*)d_in[6];
    const float* Wv   = (const float*)d_in[7];
    const float* Wo   = (const float*)d_in[8];
    const float* bo   = (const float*)d_in[9];
    const float* W1   = (const float*)d_in[10];
    const float* b1   = (const float*)d_in[11];
    const float* W2   = (const float*)d_in[12];
    const float* b2   = (const float*)d_in[13];
    const float* Wl   = (const float*)d_in[14];
    const float* bl   = (const float*)d_in[15];
    float* out = (float*)d_out;

    k_idx<<<B, 256>>>(ids);
    k_qh<<<dim3(B, LL), 256>>>(hs0, hs1, ln_g, ln_b);
    k_qp<<<dim3(8, 8, LL), 256>>>(Wq);
    k_qred<<<128, 256>>>();
    k_kqp<<<dim3(NH, 8, LL), 256>>>(Wk, ln_g, ln_b);
    k_kqred<<<1, 256>>>();
    k_scores<<<dim3(S / 256, B, LL), 256>>>(hs0, hs1);
    k_softmax<<<dim3(NH, B, LL), 256>>>();
    k_ctx<<<dim3(D / 256, B, LL), 256>>>(hs0, hs1, ln_g, ln_b);
    k_ovp<<<dim3(NH, 8, LL), 128>>>(Wv);
    k_ovred<<<128, 256>>>();
    k_wop<<<dim3(8, 8, LL), 256>>>(Wo);
    k_wored<<<128, 256>>>(bo);
    k_mlp1<<<dim3(16, 16), 256>>>(W1);
    k_gelu<<<(B * II) / 256, 256>>>(b1);
    k_mlp2<<<dim3(4, 64), 256>>>(W2);
    k_h2<<<(B * DC) / 256, 256>>>(b2);
    k_logits<<<B * 2, 256>>>(Wl, bl, out);
}

// round 11
// speedup vs baseline: 3.1955x; 1.0547x over previous
#include <cuda_runtime.h>
#include <math.h>

#define LL 2
#define B 8
#define S 2048
#define D 2048
#define NH 16
#define HD 128
#define DC 4096
#define II 16384
#define PADTOK 50257

// ---------------- scratch ----------------
__device__ int   g_idx[B];
__device__ float g_mean[LL][B][S];
__device__ float g_rstd[LL][B][S];
__device__ float g_qh[LL][B][D];
__device__ float g_qp[8][LL][B][D];      // q partials (csplit)
__device__ float g_Kg[LL][B][NH][D];     // g[d] * Kq[d]
__device__ float g_skp[8][LL][B][NH];    // partial sum g*Kq
__device__ float g_cbp[8][LL][B][NH];    // partial sum beta*Kq
__device__ float g_sc[LL][B][NH][S];     // scores, then A = w*rstd in place
__device__ float g_c0[LL][B][NH];
__device__ float g_ctx[LL][B][NH][D];
__device__ float g_ofp[8][LL][B][D];     // o_flat partials (dp split)
__device__ float g_wop[8][LL][B][D];     // wo partials (e split)
__device__ float g_attn[B][DC];
__device__ float g_p1[16][B][II];        // mlp1 partials
__device__ float g_m1[B][II];
__device__ float g_p2[64][B][DC];        // mlp2 partials
__device__ float g_h2[B][DC];

// ---------------- small kernels ----------------

__global__ void k_idx(const int* __restrict__ ids) {
    int b = blockIdx.x, t = threadIdx.x;
    __shared__ int red[256];
    int best = -1;
    for (int s = t; s < S; s += 256)
        if (ids[b * S + s] != PADTOK) best = (s > best) ? s : best;
    red[t] = best; __syncthreads();
    for (int o = 128; o; o >>= 1) { if (t < o) red[t] = max(red[t], red[t + o]); __syncthreads(); }
    if (t == 0) g_idx[b] = (red[0] < 0) ? 0 : red[0];
}

__global__ __launch_bounds__(256) void k_qh(const float* __restrict__ hs0, const float* __restrict__ hs1,
                                            const float* __restrict__ ln_g, const float* __restrict__ ln_b) {
    int b = blockIdx.x, l = blockIdx.y, t = threadIdx.x;
    const float* hs = l ? hs1 : hs0;
    int ix = g_idx[b];
    const float* row = hs + ((size_t)b * S + ix) * D;
    __shared__ float red[256];
    float s = 0.f, s2 = 0.f;
    for (int d = t; d < D; d += 256) { float v = row[d]; s += v; s2 += v * v; }
    red[t] = s; __syncthreads();
    for (int o = 128; o; o >>= 1) { if (t < o) red[t] += red[t + o]; __syncthreads(); }
    float tot = red[0]; __syncthreads();
    red[t] = s2; __syncthreads();
    for (int o = 128; o; o >>= 1) { if (t < o) red[t] += red[t + o]; __syncthreads(); }
    float tot2 = red[0]; __syncthreads();
    float mean = tot * (1.f / D);
    float var  = tot2 * (1.f / D) - mean * mean;
    float rstd = rsqrtf(var + 1e-5f);
    for (int d = t; d < D; d += 256)
        g_qh[l][b][d] = (row[d] - mean) * rstd * ln_g[l * D + d] + ln_b[l * D + d];
}

// ---------------- q projection (split over c) ----------------
__global__ __launch_bounds__(256) void k_qp(const float* __restrict__ Wq) {
    int ct = blockIdx.x, cs = blockIdx.y, l = blockIdx.z, t = threadIdx.x;
    int col = ct * 256 + t;
    int c0 = cs * 256;
    __shared__ float qs[8 * 256];
    for (int e = t; e < 2048; e += 256) { int bb = e >> 8, cc = e & 255; qs[e] = g_qh[l][bb][c0 + cc]; }
    __syncthreads();
    float acc[8] = {0,0,0,0,0,0,0,0};
#pragma unroll 4
    for (int cc = 0; cc < 256; cc++) {
        float w = Wq[(size_t)l * D * D + (size_t)(c0 + cc) * D + col];
#pragma unroll
        for (int bb = 0; bb < 8; bb++) acc[bb] += qs[bb * 256 + cc] * w;
    }
    for (int bb = 0; bb < 8; bb++) g_qp[cs][l][bb][col] = acc[bb];
}

// ---------------- Kq (split over dp); sums g_qp partials inline ----------------
__global__ __launch_bounds__(256) void k_kqp(const float* __restrict__ Wk,
                                             const float* __restrict__ ln_g, const float* __restrict__ ln_b) {
    int h = blockIdx.x, p = blockIdx.y, l = blockIdx.z, t = threadIdx.x;
    int dp = p * 256 + t;
    __shared__ __align__(16) float qs[8 * 128];
    __shared__ float red[256];
    for (int e = t; e < 1024; e += 256) {
        int bb = e >> 7, j = e & 127;
        float s = 0.f;
#pragma unroll
        for (int pp = 0; pp < 8; pp++) s += g_qp[pp][l][bb][h * 128 + j];
        qs[e] = s;
    }
    __syncthreads();
    float acc[8] = {0,0,0,0,0,0,0,0};
    const float4* wr = (const float4*)(Wk + (size_t)l * D * D + (size_t)dp * D + h * 128);
#pragma unroll 8
    for (int j4 = 0; j4 < 32; j4++) {
        float4 w = wr[j4];
#pragma unroll
        for (int bb = 0; bb < 8; bb++) {
            const float* qb = &qs[bb * 128 + j4 * 4];
            acc[bb] += qb[0] * w.x + qb[1] * w.y + qb[2] * w.z + qb[3] * w.w;
        }
    }
    float gd = ln_g[l * D + dp], bd = ln_b[l * D + dp];
    for (int bb = 0; bb < 8; bb++) {
        float kg = gd * acc[bb];
        g_Kg[l][bb][h][dp] = kg;
        red[t] = kg; __syncthreads();
        for (int o = 128; o; o >>= 1) { if (t < o) red[t] += red[t + o]; __syncthreads(); }
        if (t == 0) g_skp[p][l][bb][h] = red[0];
        __syncthreads();
        red[t] = bd * acc[bb]; __syncthreads();
        for (int o = 128; o; o >>= 1) { if (t < o) red[t] += red[t + o]; __syncthreads(); }
        if (t == 0) g_cbp[p][l][bb][h] = red[0];
        __syncthreads();
    }
}

// ---------------- scores pass: fused LN stats, software-pipelined ----------------
__global__ __launch_bounds__(256, 1) void k_scores(const float* __restrict__ hs0, const float* __restrict__ hs1) {
    int l = blockIdx.z, b = blockIdx.y;
    int s0 = blockIdx.x * 256;
    const float* hs = l ? hs1 : hs0;
    const int t = threadIdx.x;
    __shared__ __align__(16) float xs[256 * 36];
    __shared__ __align__(16) float kgs[16 * 36];
    __shared__ float smean[256], srstd[256];
    __shared__ float sskg[16], scb[16];
    if (t < 16) {
        float sk = 0.f, cc = 0.f;
#pragma unroll
        for (int p = 0; p < 8; p++) { sk += g_skp[p][l][b][t]; cc += g_cbp[p][l][b][t]; }
        sskg[t] = sk; scb[t] = cc;
    }
    const float* rowp = hs + ((size_t)b * S + s0 + t) * D;
    int kh = (t * 2) >> 5, kd = (t * 2) & 31;     // this thread fills kgs[kh][kd..kd+1]
    float rs = 0.f, rs2 = 0.f;
    float acc[4][4];
#pragma unroll
    for (int j = 0; j < 4; j++)
#pragma unroll
        for (int k = 0; k < 4; k++) acc[j][k] = 0.f;
    int sg = t >> 2, hg = t & 3;
    // prefetch chunk 0
    float4 r[8];
    {
        const float4* src = (const float4*)rowp;
#pragma unroll
        for (int q = 0; q < 8; q++) r[q] = src[q];
    }
    float kA = g_Kg[l][b][kh][kd];
    float kB = g_Kg[l][b][kh][kd + 1];
    for (int d0 = 0; d0 < D; d0 += 32) {
        // commit prefetched chunk to smem + LN stats
        float* xr = &xs[t * 36];
#pragma unroll
        for (int q = 0; q < 8; q++) {
            float4 v = r[q];
            rs  += v.x + v.y + v.z + v.w;
            rs2 += v.x * v.x + v.y * v.y + v.z * v.z + v.w * v.w;
            *((float4*)(xr + q * 4)) = v;
        }
        kgs[kh * 36 + kd] = kA;
        kgs[kh * 36 + kd + 1] = kB;
        __syncthreads();
        // prefetch next chunk (in flight during compute below)
        if (d0 + 32 < D) {
            const float4* src = (const float4*)(rowp + d0 + 32);
#pragma unroll
            for (int q = 0; q < 8; q++) r[q] = src[q];
            kA = g_Kg[l][b][kh][d0 + 32 + kd];
            kB = g_Kg[l][b][kh][d0 + 32 + kd + 1];
        }
        // compute on the committed chunk
#pragma unroll
        for (int dd = 0; dd < 32; dd += 4) {
            float4 x0 = *(const float4*)&xs[sg * 36 + dd];
            float4 x1 = *(const float4*)&xs[(sg + 64) * 36 + dd];
            float4 x2 = *(const float4*)&xs[(sg + 128) * 36 + dd];
            float4 x3 = *(const float4*)&xs[(sg + 192) * 36 + dd];
            float4 k0 = *(const float4*)&kgs[hg * 36 + dd];
            float4 k1 = *(const float4*)&kgs[(hg + 4) * 36 + dd];
            float4 k2 = *(const float4*)&kgs[(hg + 8) * 36 + dd];
            float4 k3 = *(const float4*)&kgs[(hg + 12) * 36 + dd];
#define DOT4(A, X, K) A += X.x*K.x; A += X.y*K.y; A += X.z*K.z; A += X.w*K.w;
            DOT4(acc[0][0], x0, k0) DOT4(acc[0][1], x0, k1) DOT4(acc[0][2], x0, k2) DOT4(acc[0][3], x0, k3)
            DOT4(acc[1][0], x1, k0) DOT4(acc[1][1], x1, k1) DOT4(acc[1][2], x1, k2) DOT4(acc[1][3], x1, k3)
            DOT4(acc[2][0], x2, k0) DOT4(acc[2][1], x2, k1) DOT4(acc[2][2], x2, k2) DOT4(acc[2][3], x2, k3)
            DOT4(acc[3][0], x3, k0) DOT4(acc[3][1], x3, k1) DOT4(acc[3][2], x3, k2) DOT4(acc[3][3], x3, k3)
#undef DOT4
        }
        __syncthreads();
    }
    float mean = rs * (1.f / D);
    float var  = rs2 * (1.f / D) - mean * mean;
    float rstd = rsqrtf(var + 1e-5f);
    g_mean[l][b][s0 + t] = mean;
    g_rstd[l][b][s0 + t] = rstd;
    smean[t] = mean; srstd[t] = rstd;
    __syncthreads();
#pragma unroll
    for (int j = 0; j < 4; j++) {
        int s = sg + j * 64;
        float m = smean[s], r = srstd[s];
#pragma unroll
        for (int k = 0; k < 4; k++) {
            int h = hg + k * 4;
            g_sc[l][b][h][s0 + s] = r * (acc[j][k] - m * sskg[h]) + scb[h];
        }
    }
}

// ---------------- softmax; A = w*rstd in place; c0 ----------------
__global__ __launch_bounds__(256) void k_softmax() {
    int h = blockIdx.x, b = blockIdx.y, l = blockIdx.z, t = threadIdx.x;
    float* sc = &g_sc[l][b][h][0];
    __shared__ float buf[S];
    __shared__ float red[256];
    float mx = -1e30f;
    for (int s = t; s < S; s += 256) { float v = sc[s]; buf[s] = v; mx = fmaxf(mx, v); }
    red[t] = mx; __syncthreads();
    for (int o = 128; o; o >>= 1) { if (t < o) red[t] = fmaxf(red[t], red[t + o]); __syncthreads(); }
    mx = red[0]; __syncthreads();
    float sum = 0.f;
    for (int s = t; s < S; s += 256) { float e = expf(buf[s] - mx); buf[s] = e; sum += e; }
    red[t] = sum; __syncthreads();
    for (int o = 128; o; o >>= 1) { if (t < o) red[t] += red[t + o]; __syncthreads(); }
    float inv = 1.f / red[0]; __syncthreads();
    float c0 = 0.f;
    for (int s = t; s < S; s += 256) {
        float w = buf[s] * inv;
        float r = g_rstd[l][b][s], m = g_mean[l][b][s];
        sc[s] = w * r;
        c0 += w * r * m;
    }
    red[t] = c0; __syncthreads();
    for (int o = 128; o; o >>= 1) { if (t < o) red[t] += red[t + o]; __syncthreads(); }
    if (t == 0) g_c0[l][b][h] = red[0];
}

// ---------------- ctx pass, software-pipelined ----------------
__global__ __launch_bounds__(256, 1) void k_ctx(const float* __restrict__ hs0, const float* __restrict__ hs1,
                                                const float* __restrict__ ln_g, const float* __restrict__ ln_b) {
    int l = blockIdx.z, b = blockIdx.y;
    int dt0 = blockIdx.x * 256;
    const float* hs = l ? hs1 : hs0;
    int t = threadIdx.x;
    __shared__ __align__(16) float xt[32 * 256];
    __shared__ __align__(16) float At[16 * 36];
    __shared__ float sc0[16];
    if (t < 16) sc0[t] = g_c0[l][b][t];
    int dgrp = t & 63, hgrp = t >> 6;
    int ah = (t * 2) >> 5, as_ = (t * 2) & 31;    // this thread fills At[ah][as_..as_+1]
    float4 acc[4];
#pragma unroll
    for (int k = 0; k < 4; k++) acc[k] = make_float4(0.f, 0.f, 0.f, 0.f);
    // prefetch chunk 0
    float4 r[8];
#pragma unroll
    for (int w = 0; w < 8; w++) {
        int e4 = t + w * 256;
        int row = e4 >> 6, c4 = e4 & 63;
        r[w] = *(const float4*)(hs + ((size_t)b * S + row) * D + dt0 + c4 * 4);
    }
    float aA = g_sc[l][b][ah][as_];
    float aB = g_sc[l][b][ah][as_ + 1];
    for (int s0 = 0; s0 < S; s0 += 32) {
        // commit prefetched chunk
#pragma unroll
        for (int w = 0; w < 8; w++) {
            int e4 = t + w * 256;
            int row = e4 >> 6, c4 = e4 & 63;
            *(float4*)&xt[row * 256 + c4 * 4] = r[w];
        }
        At[ah * 36 + as_] = aA;
        At[ah * 36 + as_ + 1] = aB;
        __syncthreads();
        // prefetch next chunk
        if (s0 + 32 < S) {
#pragma unroll
            for (int w = 0; w < 8; w++) {
                int e4 = t + w * 256;
                int row = e4 >> 6, c4 = e4 & 63;
                r[w] = *(const float4*)(hs + ((size_t)b * S + s0 + 32 + row) * D + dt0 + c4 * 4);
            }
            aA = g_sc[l][b][ah][s0 + 32 + as_];
            aB = g_sc[l][b][ah][s0 + 32 + as_ + 1];
        }
        // compute
#pragma unroll
        for (int ss = 0; ss < 32; ss += 4) {
            float4 xA = *(const float4*)&xt[(ss + 0) * 256 + dgrp * 4];
            float4 xB = *(const float4*)&xt[(ss + 1) * 256 + dgrp * 4];
            float4 xC = *(const float4*)&xt[(ss + 2) * 256 + dgrp * 4];
            float4 xD = *(const float4*)&xt[(ss + 3) * 256 + dgrp * 4];
#pragma unroll
            for (int k = 0; k < 4; k++) {
                float4 a = *(const float4*)&At[(hgrp + 4 * k) * 36 + ss];
                acc[k].x += xA.x * a.x; acc[k].x += xB.x * a.y; acc[k].x += xC.x * a.z; acc[k].x += xD.x * a.w;
                acc[k].y += xA.y * a.x; acc[k].y += xB.y * a.y; acc[k].y += xC.y * a.z; acc[k].y += xD.y * a.w;
                acc[k].z += xA.z * a.x; acc[k].z += xB.z * a.y; acc[k].z += xC.z * a.z; acc[k].z += xD.z * a.w;
                acc[k].w += xA.w * a.x; acc[k].w += xB.w * a.y; acc[k].w += xC.w * a.z; acc[k].w += xD.w * a.w;
            }
        }
        __syncthreads();
    }
    int d = dt0 + dgrp * 4;
    float4 gd = *(const float4*)&ln_g[l * D + d];
    float4 bd = *(const float4*)&ln_b[l * D + d];
#pragma unroll
    for (int k = 0; k < 4; k++) {
        int h = hgrp + 4 * k;
        float c0h = sc0[h];
        float4 o;
        o.x = gd.x * (acc[k].x - c0h) + bd.x;
        o.y = gd.y * (acc[k].y - c0h) + bd.y;
        o.z = gd.z * (acc[k].z - c0h) + bd.z;
        o.w = gd.w * (acc[k].w - c0h) + bd.w;
        *(float4*)&g_ctx[l][b][h][d] = o;
    }
}

// ---------------- V projection (split over dp) ----------------
__global__ __launch_bounds__(128) void k_ovp(const float* __restrict__ Wv) {
    int h = blockIdx.x, ds = blockIdx.y, l = blockIdx.z, t = threadIdx.x;
    int dp0 = ds * 256;
    __shared__ float cs_[8 * 256];
    for (int e = t; e < 2048; e += 128) { int bb = e >> 8, dd = e & 255; cs_[e] = g_ctx[l][bb][h][dp0 + dd]; }
    __syncthreads();
    float acc[8] = {0,0,0,0,0,0,0,0};
#pragma unroll 4
    for (int dp = 0; dp < 256; dp++) {
        float w = Wv[(size_t)l * D * D + (size_t)(dp0 + dp) * D + h * 128 + t];
#pragma unroll
        for (int bb = 0; bb < 8; bb++) acc[bb] += cs_[bb * 256 + dp] * w;
    }
    for (int bb = 0; bb < 8; bb++) g_ofp[ds][l][bb][h * 128 + t] = acc[bb];
}

// ---------------- Wo projection (split over e); sums g_ofp partials inline ----------------
__global__ __launch_bounds__(256) void k_wop(const float* __restrict__ Wo) {
    int ct = blockIdx.x, es = blockIdx.y, l = blockIdx.z, t = threadIdx.x;
    int col = ct * 256 + t;
    int e0 = es * 256;
    __shared__ float os[8 * 256];
    for (int e = t; e < 2048; e += 256) {
        int bb = e >> 8, ee = e & 255;
        float s = 0.f;
#pragma unroll
        for (int pp = 0; pp < 8; pp++) s += g_ofp[pp][l][bb][e0 + ee];
        os[e] = s;
    }
    __syncthreads();
    float acc[8] = {0,0,0,0,0,0,0,0};
#pragma unroll 4
    for (int ee = 0; ee < 256; ee++) {
        float w = Wo[(size_t)l * D * D + (size_t)(e0 + ee) * D + col];
#pragma unroll
        for (int bb = 0; bb < 8; bb++) acc[bb] += os[bb * 256 + ee] * w;
    }
    for (int bb = 0; bb < 8; bb++) g_wop[es][l][bb][col] = acc[bb];
}

__global__ void k_wored(const float* __restrict__ bo) {
    int idx = blockIdx.x * 256 + threadIdx.x;  // LL*B*D
    int l = idx >> 14, r = idx & 16383, b = r >> 11, col = r & 2047;
    float s = bo[l * D + col];
#pragma unroll
    for (int p = 0; p < 8; p++) s += g_wop[p][l][b][col];
    g_attn[b][l * D + col] = s;
}

// ---------------- MLP ----------------
__global__ __launch_bounds__(256) void k_mlp1(const float* __restrict__ W1) {
    int it = blockIdx.x;   // 0..15 -> 256 float4-cols each
    int cs = blockIdx.y;   // 0..15 -> 256 rows each
    int t = threadIdx.x;
    int col4 = it * 256 + t;
    int cbase = cs * 256;
    __shared__ float as[8 * 256];
    for (int e = t; e < 2048; e += 256) { int bb = e >> 8, cc = e & 255; as[e] = g_attn[bb][cbase + cc]; }
    __syncthreads();
    float4 acc[8];
#pragma unroll
    for (int bb = 0; bb < 8; bb++) acc[bb] = make_float4(0.f, 0.f, 0.f, 0.f);
#pragma unroll 4
    for (int cc = 0; cc < 256; cc++) {
        float4 w = *(const float4*)(W1 + (size_t)(cbase + cc) * II + col4 * 4);
#pragma unroll
        for (int bb = 0; bb < 8; bb++) {
            float av = as[bb * 256 + cc];
            acc[bb].x += av * w.x; acc[bb].y += av * w.y; acc[bb].z += av * w.z; acc[bb].w += av * w.w;
        }
    }
    for (int bb = 0; bb < 8; bb++) *(float4*)&g_p1[cs][bb][col4 * 4] = acc[bb];
}

__global__ void k_gelu(const float* __restrict__ b1) {
    int e = blockIdx.x * 256 + threadIdx.x;
    int bb = e / II, i = e % II;
    float x = b1[i];
#pragma unroll
    for (int p = 0; p < 16; p++) x += g_p1[p][bb][i];
    g_m1[bb][i] = 0.5f * x * (1.0f + erff(x * 0.70710678118654752f));
}

__global__ __launch_bounds__(256) void k_mlp2(const float* __restrict__ W2) {
    int ct = blockIdx.x;   // 0..3 -> 256 float4-cols each
    int isp = blockIdx.y;  // 0..63 -> 256 rows each
    int t = threadIdx.x;
    int col4 = ct * 256 + t;
    int ibase = isp * 256;
    __shared__ float ms[8 * 256];
    for (int e = t; e < 2048; e += 256) { int bb = e >> 8, ii = e & 255; ms[e] = g_m1[bb][ibase + ii]; }
    __syncthreads();
    float4 acc[8];
#pragma unroll
    for (int bb = 0; bb < 8; bb++) acc[bb] = make_float4(0.f, 0.f, 0.f, 0.f);
#pragma unroll 4
    for (int ii = 0; ii < 256; ii++) {
        float4 w = *(const float4*)(W2 + (size_t)(ibase + ii) * DC + col4 * 4);
#pragma unroll
        for (int bb = 0; bb < 8; bb++) {
            float mv = ms[bb * 256 + ii];
            acc[bb].x += mv * w.x; acc[bb].y += mv * w.y; acc[bb].z += mv * w.z; acc[bb].w += mv * w.w;
        }
    }
    for (int bb = 0; bb < 8; bb++) *(float4*)&g_p2[isp][bb][col4 * 4] = acc[bb];
}

__global__ void k_h2(const float* __restrict__ b2) {
    int e = blockIdx.x * 256 + threadIdx.x;
    int bb = e / DC, c = e % DC;
    float s = g_attn[bb][c] + b2[c];
#pragma unroll
    for (int i = 0; i < 64; i++) s += g_p2[i][bb][c];
    g_h2[bb][c] = s;
}

__global__ __launch_bounds__(256) void k_logits(const float* __restrict__ Wl, const float* __restrict__ bl,
                                                float* __restrict__ out) {
    int b = blockIdx.x >> 1, j = blockIdx.x & 1, t = threadIdx.x;
    __shared__ float red[256];
    float s = 0.f;
    for (int c = t; c < DC; c += 256) s += g_h2[b][c] * Wl[c * 2 + j];
    red[t] = s; __syncthreads();
    for (int o = 128; o; o >>= 1) { if (t < o) red[t] += red[t + o]; __syncthreads(); }
    if (t == 0) out[b * 2 + j] = red[0] + bl[j];
}

// ---------------- launch ----------------
extern "C" void kernel_launch(void* const* d_in, const int* in_sizes, int n_in,
                              void* d_out, int out_size) {
    const float* hs0  = (const float*)d_in[0];
    const float* hs1  = (const float*)d_in[1];
    const int*   ids  = (const int*)  d_in[2];
    const float* ln_g = (const float*)d_in[3];
    const float* ln_b = (const float*)d_in[4];
    const float* Wq   = (const float*)d_in[5];
    const float* Wk   = (const float*)d_in[6];
    const float* Wv   = (const float*)d_in[7];
    const float* Wo   = (const float*)d_in[8];
    const float* bo   = (const float*)d_in[9];
    const float* W1   = (const float*)d_in[10];
    const float* b1   = (const float*)d_in[11];
    const float* W2   = (const float*)d_in[12];
    const float* b2   = (const float*)d_in[13];
    const float* Wl   = (const float*)d_in[14];
    const float* bl   = (const float*)d_in[15];
    float* out = (float*)d_out;

    k_idx<<<B, 256>>>(ids);
    k_qh<<<dim3(B, LL), 256>>>(hs0, hs1, ln_g, ln_b);
    k_qp<<<dim3(8, 8, LL), 256>>>(Wq);
    k_kqp<<<dim3(NH, 8, LL), 256>>>(Wk, ln_g, ln_b);
    k_scores<<<dim3(S / 256, B, LL), 256>>>(hs0, hs1);
    k_softmax<<<dim3(NH, B, LL), 256>>>();
    k_ctx<<<dim3(D / 256, B, LL), 256>>>(hs0, hs1, ln_g, ln_b);
    k_ovp<<<dim3(NH, 8, LL), 128>>>(Wv);
    k_wop<<<dim3(8, 8, LL), 256>>>(Wo);
    k_wored<<<128, 256>>>(bo);
    k_mlp1<<<dim3(16, 16), 256>>>(W1);
    k_gelu<<<(B * II) / 256, 256>>>(b1);
    k_mlp2<<<dim3(4, 64), 256>>>(W2);
    k_h2<<<(B * DC) / 256, 256>>>(b2);
    k_logits<<<B * 2, 256>>>(Wl, bl, out);
}

// round 13
// speedup vs baseline: 3.6800x; 1.1516x over previous
#include <cuda_runtime.h>
#include <math.h>

#define LL 2
#define B 8
#define S 2048
#define D 2048
#define NH 16
#define HD 128
#define DC 4096
#define II 16384
#define PADTOK 50257

// ---------------- scratch ----------------
__device__ int   g_idx[B];
__device__ float g_mean[LL][B][S];
__device__ float g_rstd[LL][B][S];
__device__ float g_qh[LL][B][D];
__device__ float g_qp[8][LL][B][D];      // q partials (csplit)
__device__ float g_Kg[LL][B][NH][D];     // g[d] * Kq[d]
__device__ float g_skp[8][LL][B][NH];    // partial sum g*Kq
__device__ float g_cbp[8][LL][B][NH];    // partial sum beta*Kq
__device__ float g_sc[LL][B][NH][S];     // scores, then A = w*rstd in place
__device__ float g_c0[LL][B][NH];
__device__ float g_ctx[LL][B][NH][D];
__device__ float g_ofp[8][LL][B][D];     // o_flat partials (dp split)
__device__ float g_wop[8][LL][B][D];     // wo partials (e split)
__device__ float g_attn[B][DC];
__device__ float g_p1[16][B][II];        // mlp1 partials
__device__ float g_m1[B][II];
__device__ float g_p2[64][B][DC];        // mlp2 partials
__device__ float g_h2[B][DC];

// ---------------- small kernels ----------------

__global__ void k_idx(const int* __restrict__ ids) {
    int b = blockIdx.x, t = threadIdx.x;
    __shared__ int red[256];
    int best = -1;
    for (int s = t; s < S; s += 256)
        if (ids[b * S + s] != PADTOK) best = (s > best) ? s : best;
    red[t] = best; __syncthreads();
    for (int o = 128; o; o >>= 1) { if (t < o) red[t] = max(red[t], red[t + o]); __syncthreads(); }
    if (t == 0) g_idx[b] = (red[0] < 0) ? 0 : red[0];
}

__global__ __launch_bounds__(256) void k_qh(const float* __restrict__ hs0, const float* __restrict__ hs1,
                                            const float* __restrict__ ln_g, const float* __restrict__ ln_b) {
    int b = blockIdx.x, l = blockIdx.y, t = threadIdx.x;
    const float* hs = l ? hs1 : hs0;
    int ix = g_idx[b];
    const float* row = hs + ((size_t)b * S + ix) * D;
    __shared__ float red[256];
    float s = 0.f, s2 = 0.f;
    for (int d = t; d < D; d += 256) { float v = row[d]; s += v; s2 += v * v; }
    red[t] = s; __syncthreads();
    for (int o = 128; o; o >>= 1) { if (t < o) red[t] += red[t + o]; __syncthreads(); }
    float tot = red[0]; __syncthreads();
    red[t] = s2; __syncthreads();
    for (int o = 128; o; o >>= 1) { if (t < o) red[t] += red[t + o]; __syncthreads(); }
    float tot2 = red[0]; __syncthreads();
    float mean = tot * (1.f / D);
    float var  = tot2 * (1.f / D) - mean * mean;
    float rstd = rsqrtf(var + 1e-5f);
    for (int d = t; d < D; d += 256)
        g_qh[l][b][d] = (row[d] - mean) * rstd * ln_g[l * D + d] + ln_b[l * D + d];
}

// ---------------- q projection: float4 weight stream, stripe reduce ----------------
__global__ __launch_bounds__(256) void k_qp(const float* __restrict__ Wq) {
    int ct = blockIdx.x, cs = blockIdx.y, l = blockIdx.z, t = threadIdx.x;
    int tr = t >> 6, la = t & 63;              // 4 row-stripes x 64 f4-cols
    __shared__ float qsh[8 * 256];
    __shared__ __align__(16) float4 rbuf[2048];   // [tr][bb][la]
    int c0 = cs * 256;
    for (int e = t; e < 2048; e += 256) { int bb = e >> 8, cc = e & 255; qsh[e] = g_qh[l][bb][c0 + cc]; }
    __syncthreads();
    float4 acc[8];
#pragma unroll
    for (int bb = 0; bb < 8; bb++) acc[bb] = make_float4(0.f, 0.f, 0.f, 0.f);
    const float* Wb = Wq + (size_t)l * D * D + (size_t)c0 * D + ct * 256 + la * 4;
#pragma unroll 8
    for (int i = 0; i < 64; i++) {
        int cc = i * 4 + tr;
        float4 wv = *(const float4*)(Wb + (size_t)cc * D);
#pragma unroll
        for (int bb = 0; bb < 8; bb++) {
            float a = qsh[bb * 256 + cc];
            acc[bb].x += a * wv.x; acc[bb].y += a * wv.y; acc[bb].z += a * wv.z; acc[bb].w += a * wv.w;
        }
    }
#pragma unroll
    for (int bb = 0; bb < 8; bb++) rbuf[(tr * 8 + bb) * 64 + la] = acc[bb];
    __syncthreads();
#pragma unroll
    for (int k = 0; k < 2; k++) {
        int o = t + k * 256;
        int bb = o >> 6, la2 = o & 63;
        float4 v  = rbuf[(0 * 8 + bb) * 64 + la2];
        float4 v1 = rbuf[(1 * 8 + bb) * 64 + la2];
        float4 v2 = rbuf[(2 * 8 + bb) * 64 + la2];
        float4 v3 = rbuf[(3 * 8 + bb) * 64 + la2];
        v.x += v1.x + v2.x + v3.x;
        v.y += v1.y + v2.y + v3.y;
        v.z += v1.z + v2.z + v3.z;
        v.w += v1.w + v2.w + v3.w;
        *(float4*)&g_qp[cs][l][bb][ct * 256 + la2 * 4] = v;
    }
}

// ---------------- Kq: warp-per-row coalesced, shuffle reduce ----------------
__global__ __launch_bounds__(256) void k_kqp(const float* __restrict__ Wk,
                                             const float* __restrict__ ln_g, const float* __restrict__ ln_b) {
    int h = blockIdx.x, p = blockIdx.y, l = blockIdx.z, t = threadIdx.x;
    int w = t >> 5, la = t & 31;
    __shared__ __align__(16) float qs[8 * 128];
    __shared__ float sred[8][16];
    for (int e = t; e < 1024; e += 256) {
        int bb = e >> 7, j = e & 127;
        float s = 0.f;
#pragma unroll
        for (int pp = 0; pp < 8; pp++) s += g_qp[pp][l][bb][h * 128 + j];
        qs[e] = s;
    }
    __syncthreads();
    float4 qreg[8];
#pragma unroll
    for (int bb = 0; bb < 8; bb++) qreg[bb] = *(const float4*)&qs[bb * 128 + la * 4];
    float skpA[8] = {0,0,0,0,0,0,0,0}, cbpA[8] = {0,0,0,0,0,0,0,0};
    const float* Wb = Wk + (size_t)l * D * D + (size_t)(p * 256) * D + h * 128 + la * 4;
#pragma unroll 2
    for (int i = 0; i < 32; i++) {
        int dpl = i * 8 + w;
        int dp = p * 256 + dpl;
        float4 wv = *(const float4*)(Wb + (size_t)dpl * D);
        float kq[8];
#pragma unroll
        for (int bb = 0; bb < 8; bb++)
            kq[bb] = qreg[bb].x * wv.x + qreg[bb].y * wv.y + qreg[bb].z * wv.z + qreg[bb].w * wv.w;
#pragma unroll
        for (int off = 16; off; off >>= 1)
#pragma unroll
            for (int bb = 0; bb < 8; bb++)
                kq[bb] += __shfl_xor_sync(0xffffffffu, kq[bb], off);
        float gd = ln_g[l * D + dp], bd = ln_b[l * D + dp];
        if (la == 0) {
            float* kp = &g_Kg[l][0][h][dp];
#pragma unroll
            for (int bb = 0; bb < 8; bb++) kp[(size_t)bb * NH * D] = gd * kq[bb];
        }
#pragma unroll
        for (int bb = 0; bb < 8; bb++) { skpA[bb] += gd * kq[bb]; cbpA[bb] += bd * kq[bb]; }
    }
    if (la == 0) {
#pragma unroll
        for (int bb = 0; bb < 8; bb++) { sred[w][bb] = skpA[bb]; sred[w][8 + bb] = cbpA[bb]; }
    }
    __syncthreads();
    if (t < 16) {
        float s = 0.f;
#pragma unroll
        for (int ww = 0; ww < 8; ww++) s += sred[ww][t];
        if (t < 8) g_skp[p][l][t][h] = s;
        else       g_cbp[p][l][t - 8][h] = s;
    }
}

// ---------------- scores pass: fused LN stats, software-pipelined ----------------
__global__ __launch_bounds__(256, 1) void k_scores(const float* __restrict__ hs0, const float* __restrict__ hs1) {
    int l = blockIdx.z, b = blockIdx.y;
    int s0 = blockIdx.x * 256;
    const float* hs = l ? hs1 : hs0;
    const int t = threadIdx.x;
    __shared__ __align__(16) float xs[256 * 36];
    __shared__ __align__(16) float kgs[16 * 36];
    __shared__ float smean[256], srstd[256];
    __shared__ float sskg[16], scb[16];
    if (t < 16) {
        float sk = 0.f, cc = 0.f;
#pragma unroll
        for (int p = 0; p < 8; p++) { sk += g_skp[p][l][b][t]; cc += g_cbp[p][l][b][t]; }
        sskg[t] = sk; scb[t] = cc;
    }
    const float* rowp = hs + ((size_t)b * S + s0 + t) * D;
    int kh = (t * 2) >> 5, kd = (t * 2) & 31;
    float rs = 0.f, rs2 = 0.f;
    float acc[4][4];
#pragma unroll
    for (int j = 0; j < 4; j++)
#pragma unroll
        for (int k = 0; k < 4; k++) acc[j][k] = 0.f;
    int sg = t >> 2, hg = t & 3;
    float4 r[8];
    {
        const float4* src = (const float4*)rowp;
#pragma unroll
        for (int q = 0; q < 8; q++) r[q] = src[q];
    }
    float kA = g_Kg[l][b][kh][kd];
    float kB = g_Kg[l][b][kh][kd + 1];
    for (int d0 = 0; d0 < D; d0 += 32) {
        float* xr = &xs[t * 36];
#pragma unroll
        for (int q = 0; q < 8; q++) {
            float4 v = r[q];
            rs  += v.x + v.y + v.z + v.w;
            rs2 += v.x * v.x + v.y * v.y + v.z * v.z + v.w * v.w;
            *((float4*)(xr + q * 4)) = v;
        }
        kgs[kh * 36 + kd] = kA;
        kgs[kh * 36 + kd + 1] = kB;
        __syncthreads();
        if (d0 + 32 < D) {
            const float4* src = (const float4*)(rowp + d0 + 32);
#pragma unroll
            for (int q = 0; q < 8; q++) r[q] = src[q];
            kA = g_Kg[l][b][kh][d0 + 32 + kd];
            kB = g_Kg[l][b][kh][d0 + 32 + kd + 1];
        }
#pragma unroll
        for (int dd = 0; dd < 32; dd += 4) {
            float4 x0 = *(const float4*)&xs[sg * 36 + dd];
            float4 x1 = *(const float4*)&xs[(sg + 64) * 36 + dd];
            float4 x2 = *(const float4*)&xs[(sg + 128) * 36 + dd];
            float4 x3 = *(const float4*)&xs[(sg + 192) * 36 + dd];
            float4 k0 = *(const float4*)&kgs[hg * 36 + dd];
            float4 k1 = *(const float4*)&kgs[(hg + 4) * 36 + dd];
            float4 k2 = *(const float4*)&kgs[(hg + 8) * 36 + dd];
            float4 k3 = *(const float4*)&kgs[(hg + 12) * 36 + dd];
#define DOT4(A, X, K) A += X.x*K.x; A += X.y*K.y; A += X.z*K.z; A += X.w*K.w;
            DOT4(acc[0][0], x0, k0) DOT4(acc[0][1], x0, k1) DOT4(acc[0][2], x0, k2) DOT4(acc[0][3], x0, k3)
            DOT4(acc[1][0], x1, k0) DOT4(acc[1][1], x1, k1) DOT4(acc[1][2], x1, k2) DOT4(acc[1][3], x1, k3)
            DOT4(acc[2][0], x2, k0) DOT4(acc[2][1], x2, k1) DOT4(acc[2][2], x2, k2) DOT4(acc[2][3], x2, k3)
            DOT4(acc[3][0], x3, k0) DOT4(acc[3][1], x3, k1) DOT4(acc[3][2], x3, k2) DOT4(acc[3][3], x3, k3)
#undef DOT4
        }
        __syncthreads();
    }
    float mean = rs * (1.f / D);
    float var  = rs2 * (1.f / D) - mean * mean;
    float rstd = rsqrtf(var + 1e-5f);
    g_mean[l][b][s0 + t] = mean;
    g_rstd[l][b][s0 + t] = rstd;
    smean[t] = mean; srstd[t] = rstd;
    __syncthreads();
#pragma unroll
    for (int j = 0; j < 4; j++) {
        int s = sg + j * 64;
        float m = smean[s], r2 = srstd[s];
#pragma unroll
        for (int k = 0; k < 4; k++) {
            int h = hg + k * 4;
            g_sc[l][b][h][s0 + s] = r2 * (acc[j][k] - m * sskg[h]) + scb[h];
        }
    }
}

// ---------------- softmax; A = w*rstd in place; c0 ----------------
__global__ __launch_bounds__(256) void k_softmax() {
    int h = blockIdx.x, b = blockIdx.y, l = blockIdx.z, t = threadIdx.x;
    float* sc = &g_sc[l][b][h][0];
    __shared__ float buf[S];
    __shared__ float red[256];
    float mx = -1e30f;
    for (int s = t; s < S; s += 256) { float v = sc[s]; buf[s] = v; mx = fmaxf(mx, v); }
    red[t] = mx; __syncthreads();
    for (int o = 128; o; o >>= 1) { if (t < o) red[t] = fmaxf(red[t], red[t + o]); __syncthreads(); }
    mx = red[0]; __syncthreads();
    float sum = 0.f;
    for (int s = t; s < S; s += 256) { float e = expf(buf[s] - mx); buf[s] = e; sum += e; }
    red[t] = sum; __syncthreads();
    for (int o = 128; o; o >>= 1) { if (t < o) red[t] += red[t + o]; __syncthreads(); }
    float inv = 1.f / red[0]; __syncthreads();
    float c0 = 0.f;
    for (int s = t; s < S; s += 256) {
        float w = buf[s] * inv;
        float r = g_rstd[l][b][s], m = g_mean[l][b][s];
        sc[s] = w * r;
        c0 += w * r * m;
    }
    red[t] = c0; __syncthreads();
    for (int o = 128; o; o >>= 1) { if (t < o) red[t] += red[t + o]; __syncthreads(); }
    if (t == 0) g_c0[l][b][h] = red[0];
}

// ---------------- ctx pass, software-pipelined ----------------
__global__ __launch_bounds__(256, 1) void k_ctx(const float* __restrict__ hs0, const float* __restrict__ hs1,
                                                const float* __restrict__ ln_g, const float* __restrict__ ln_b) {
    int l = blockIdx.z, b = blockIdx.y;
    int dt0 = blockIdx.x * 256;
    const float* hs = l ? hs1 : hs0;
    int t = threadIdx.x;
    __shared__ __align__(16) float xt[32 * 256];
    __shared__ __align__(16) float At[16 * 36];
    __shared__ float sc0[16];
    if (t < 16) sc0[t] = g_c0[l][b][t];
    int dgrp = t & 63, hgrp = t >> 6;
    int ah = (t * 2) >> 5, as_ = (t * 2) & 31;
    float4 acc[4];
#pragma unroll
    for (int k = 0; k < 4; k++) acc[k] = make_float4(0.f, 0.f, 0.f, 0.f);
    float4 r[8];
#pragma unroll
    for (int w = 0; w < 8; w++) {
        int e4 = t + w * 256;
        int row = e4 >> 6, c4 = e4 & 63;
        r[w] = *(const float4*)(hs + ((size_t)b * S + row) * D + dt0 + c4 * 4);
    }
    float aA = g_sc[l][b][ah][as_];
    float aB = g_sc[l][b][ah][as_ + 1];
    for (int s0 = 0; s0 < S; s0 += 32) {
#pragma unroll
        for (int w = 0; w < 8; w++) {
            int e4 = t + w * 256;
            int row = e4 >> 6, c4 = e4 & 63;
            *(float4*)&xt[row * 256 + c4 * 4] = r[w];
        }
        At[ah * 36 + as_] = aA;
        At[ah * 36 + as_ + 1] = aB;
        __syncthreads();
        if (s0 + 32 < S) {
#pragma unroll
            for (int w = 0; w < 8; w++) {
                int e4 = t + w * 256;
                int row = e4 >> 6, c4 = e4 & 63;
                r[w] = *(const float4*)(hs + ((size_t)b * S + s0 + 32 + row) * D + dt0 + c4 * 4);
            }
            aA = g_sc[l][b][ah][s0 + 32 + as_];
            aB = g_sc[l][b][ah][s0 + 32 + as_ + 1];
        }
#pragma unroll
        for (int ss = 0; ss < 32; ss += 4) {
            float4 xA = *(const float4*)&xt[(ss + 0) * 256 + dgrp * 4];
            float4 xB = *(const float4*)&xt[(ss + 1) * 256 + dgrp * 4];
            float4 xC = *(const float4*)&xt[(ss + 2) * 256 + dgrp * 4];
            float4 xD = *(const float4*)&xt[(ss + 3) * 256 + dgrp * 4];
#pragma unroll
            for (int k = 0; k < 4; k++) {
                float4 a = *(const float4*)&At[(hgrp + 4 * k) * 36 + ss];
                acc[k].x += xA.x * a.x; acc[k].x += xB.x * a.y; acc[k].x += xC.x * a.z; acc[k].x += xD.x * a.w;
                acc[k].y += xA.y * a.x; acc[k].y += xB.y * a.y; acc[k].y += xC.y * a.z; acc[k].y += xD.y * a.w;
                acc[k].z += xA.z * a.x; acc[k].z += xB.z * a.y; acc[k].z += xC.z * a.z; acc[k].z += xD.z * a.w;
                acc[k].w += xA.w * a.x; acc[k].w += xB.w * a.y; acc[k].w += xC.w * a.z; acc[k].w += xD.w * a.w;
            }
        }
        __syncthreads();
    }
    int d = dt0 + dgrp * 4;
    float4 gd = *(const float4*)&ln_g[l * D + d];
    float4 bd = *(const float4*)&ln_b[l * D + d];
#pragma unroll
    for (int k = 0; k < 4; k++) {
        int h = hgrp + 4 * k;
        float c0h = sc0[h];
        float4 o;
        o.x = gd.x * (acc[k].x - c0h) + bd.x;
        o.y = gd.y * (acc[k].y - c0h) + bd.y;
        o.z = gd.z * (acc[k].z - c0h) + bd.z;
        o.w = gd.w * (acc[k].w - c0h) + bd.w;
        *(float4*)&g_ctx[l][b][h][d] = o;
    }
}

// ---------------- V projection: warp-per-row float4, stripe reduce ----------------
__global__ __launch_bounds__(256) void k_ovp(const float* __restrict__ Wv) {
    int h = blockIdx.x, ds = blockIdx.y, l = blockIdx.z, t = threadIdx.x;
    int w = t >> 5, la = t & 31;
    int dp0 = ds * 256;
    __shared__ float cs_[8 * 256];
    __shared__ __align__(16) float4 part[2048];    // [w][bb][la]
    for (int e = t; e < 2048; e += 256) { int bb = e >> 8, dd = e & 255; cs_[e] = g_ctx[l][bb][h][dp0 + dd]; }
    __syncthreads();
    float4 acc[8];
#pragma unroll
    for (int bb = 0; bb < 8; bb++) acc[bb] = make_float4(0.f, 0.f, 0.f, 0.f);
    const float* Wb = Wv + (size_t)l * D * D + (size_t)dp0 * D + h * 128 + la * 4;
#pragma unroll 4
    for (int i = 0; i < 32; i++) {
        int dpl = i * 8 + w;
        float4 wv = *(const float4*)(Wb + (size_t)dpl * D);
#pragma unroll
        for (int bb = 0; bb < 8; bb++) {
            float a = cs_[bb * 256 + dpl];
            acc[bb].x += a * wv.x; acc[bb].y += a * wv.y; acc[bb].z += a * wv.z; acc[bb].w += a * wv.w;
        }
    }
#pragma unroll
    for (int bb = 0; bb < 8; bb++) part[(w * 8 + bb) * 32 + la] = acc[bb];
    __syncthreads();
    {
        int bb = t >> 5, la2 = t & 31;
        float4 v = part[(0 * 8 + bb) * 32 + la2];
#pragma unroll
        for (int ww = 1; ww < 8; ww++) {
            float4 u = part[(ww * 8 + bb) * 32 + la2];
            v.x += u.x; v.y += u.y; v.z += u.z; v.w += u.w;
        }
        *(float4*)&g_ofp[ds][l][bb][h * 128 + la2 * 4] = v;
    }
}

// ---------------- Wo projection: float4 stream, sums g_ofp inline ----------------
__global__ __launch_bounds__(256) void k_wop(const float* __restrict__ Wo) {
    int ct = blockIdx.x, es = blockIdx.y, l = blockIdx.z, t = threadIdx.x;
    int tr = t >> 6, la = t & 63;
    int e0 = es * 256;
    __shared__ __align__(16) float os[8 * 256];
    __shared__ __align__(16) float4 rbuf[2048];
    for (int e = t; e < 512; e += 256) {
        int bb = e >> 6, ee4 = e & 63;
        float4 s = make_float4(0.f, 0.f, 0.f, 0.f);
#pragma unroll
        for (int pp = 0; pp < 8; pp++) {
            float4 u = *(const float4*)&g_ofp[pp][l][bb][e0 + ee4 * 4];
            s.x += u.x; s.y += u.y; s.z += u.z; s.w += u.w;
        }
        *(float4*)&os[bb * 256 + ee4 * 4] = s;
    }
    __syncthreads();
    float4 acc[8];
#pragma unroll
    for (int bb = 0; bb < 8; bb++) acc[bb] = make_float4(0.f, 0.f, 0.f, 0.f);
    const float* Wb = Wo + (size_t)l * D * D + (size_t)e0 * D + ct * 256 + la * 4;
#pragma unroll 8
    for (int i = 0; i < 64; i++) {
        int ee = i * 4 + tr;
        float4 wv = *(const float4*)(Wb + (size_t)ee * D);
#pragma unroll
        for (int bb = 0; bb < 8; bb++) {
            float a = os[bb * 256 + ee];
            acc[bb].x += a * wv.x; acc[bb].y += a * wv.y; acc[bb].z += a * wv.z; acc[bb].w += a * wv.w;
        }
    }
#pragma unroll
    for (int bb = 0; bb < 8; bb++) rbuf[(tr * 8 + bb) * 64 + la] = acc[bb];
    __syncthreads();
#pragma unroll
    for (int k = 0; k < 2; k++) {
        int o = t + k * 256;
        int bb = o >> 6, la2 = o & 63;
        float4 v  = rbuf[(0 * 8 + bb) * 64 + la2];
        float4 v1 = rbuf[(1 * 8 + bb) * 64 + la2];
        float4 v2 = rbuf[(2 * 8 + bb) * 64 + la2];
        float4 v3 = rbuf[(3 * 8 + bb) * 64 + la2];
        v.x += v1.x + v2.x + v3.x;
        v.y += v1.y + v2.y + v3.y;
        v.z += v1.z + v2.z + v3.z;
        v.w += v1.w + v2.w + v3.w;
        *(float4*)&g_wop[es][l][bb][ct * 256 + la2 * 4] = v;
    }
}

__global__ void k_wored(const float* __restrict__ bo) {
    int idx = blockIdx.x * 256 + threadIdx.x;  // LL*B*D
    int l = idx >> 14, r = idx & 16383, b = r >> 11, col = r & 2047;
    float s = bo[l * D + col];
#pragma unroll
    for (int p = 0; p < 8; p++) s += g_wop[p][l][b][col];
    g_attn[b][l * D + col] = s;
}

// ---------------- MLP: dual-row load streams ----------------
__global__ __launch_bounds__(256) void k_mlp1(const float* __restrict__ W1) {
    int it = blockIdx.x;   // 0..15 -> 256 float4-cols each
    int cs = blockIdx.y;   // 0..15 -> 256 rows each
    int t = threadIdx.x;
    int col4 = it * 256 + t;
    int cbase = cs * 256;
    __shared__ float as[8 * 256];
    for (int e = t; e < 2048; e += 256) { int bb = e >> 8, cc = e & 255; as[e] = g_attn[bb][cbase + cc]; }
    __syncthreads();
    float4 acc[8];
#pragma unroll
    for (int bb = 0; bb < 8; bb++) acc[bb] = make_float4(0.f, 0.f, 0.f, 0.f);
#pragma unroll 4
    for (int cc = 0; cc < 128; cc++) {
        float4 wa = *(const float4*)(W1 + (size_t)(cbase + cc) * II + col4 * 4);
        float4 wb = *(const float4*)(W1 + (size_t)(cbase + 128 + cc) * II + col4 * 4);
#pragma unroll
        for (int bb = 0; bb < 8; bb++) {
            float av = as[bb * 256 + cc];
            float bv = as[bb * 256 + 128 + cc];
            acc[bb].x += av * wa.x + bv * wb.x;
            acc[bb].y += av * wa.y + bv * wb.y;
            acc[bb].z += av * wa.z + bv * wb.z;
            acc[bb].w += av * wa.w + bv * wb.w;
        }
    }
    for (int bb = 0; bb < 8; bb++) *(float4*)&g_p1[cs][bb][col4 * 4] = acc[bb];
}

__global__ void k_gelu(const float* __restrict__ b1) {
    int e = blockIdx.x * 256 + threadIdx.x;
    int bb = e / II, i = e % II;
    float x = b1[i];
#pragma unroll
    for (int p = 0; p < 16; p++) x += g_p1[p][bb][i];
    g_m1[bb][i] = 0.5f * x * (1.0f + erff(x * 0.70710678118654752f));
}

__global__ __launch_bounds__(256) void k_mlp2(const float* __restrict__ W2) {
    int ct = blockIdx.x;   // 0..3 -> 256 float4-cols each
    int isp = blockIdx.y;  // 0..63 -> 256 rows each
    int t = threadIdx.x;
    int col4 = ct * 256 + t;
    int ibase = isp * 256;
    __shared__ float ms[8 * 256];
    for (int e = t; e < 2048; e += 256) { int bb = e >> 8, ii = e & 255; ms[e] = g_m1[bb][ibase + ii]; }
    __syncthreads();
    float4 acc[8];
#pragma unroll
    for (int bb = 0; bb < 8; bb++) acc[bb] = make_float4(0.f, 0.f, 0.f, 0.f);
#pragma unroll 4
    for (int ii = 0; ii < 128; ii++) {
        float4 wa = *(const float4*)(W2 + (size_t)(ibase + ii) * DC + col4 * 4);
        float4 wb = *(const float4*)(W2 + (size_t)(ibase + 128 + ii) * DC + col4 * 4);
#pragma unroll
        for (int bb = 0; bb < 8; bb++) {
            float av = ms[bb * 256 + ii];
            float bv = ms[bb * 256 + 128 + ii];
            acc[bb].x += av * wa.x + bv * wb.x;
            acc[bb].y += av * wa.y + bv * wb.y;
            acc[bb].z += av * wa.z + bv * wb.z;
            acc[bb].w += av * wa.w + bv * wb.w;
        }
    }
    for (int bb = 0; bb < 8; bb++) *(float4*)&g_p2[isp][bb][col4 * 4] = acc[bb];
}

__global__ void k_h2(const float* __restrict__ b2) {
    int e = blockIdx.x * 256 + threadIdx.x;
    int bb = e / DC, c = e % DC;
    float s = g_attn[bb][c] + b2[c];
#pragma unroll
    for (int i = 0; i < 64; i++) s += g_p2[i][bb][c];
    g_h2[bb][c] = s;
}

__global__ __launch_bounds__(256) void k_logits(const float* __restrict__ Wl, const float* __restrict__ bl,
                                                float* __restrict__ out) {
    int b = blockIdx.x >> 1, j = blockIdx.x & 1, t = threadIdx.x;
    __shared__ float red[256];
    float s = 0.f;
    for (int c = t; c < DC; c += 256) s += g_h2[b][c] * Wl[c * 2 + j];
    red[t] = s; __syncthreads();
    for (int o = 128; o; o >>= 1) { if (t < o) red[t] += red[t + o]; __syncthreads(); }
    if (t == 0) out[b * 2 + j] = red[0] + bl[j];
}

// ---------------- launch ----------------
extern "C" void kernel_launch(void* const* d_in, const int* in_sizes, int n_in,
                              void* d_out, int out_size) {
    const float* hs0  = (const float*)d_in[0];
    const float* hs1  = (const float*)d_in[1];
    const int*   ids  = (const int*)  d_in[2];
    const float* ln_g = (const float*)d_in[3];
    const float* ln_b = (const float*)d_in[4];
    const float* Wq   = (const float*)d_in[5];
    const float* Wk   = (const float*)d_in[6];
    const float* Wv   = (const float*)d_in[7];
    const float* Wo   = (const float*)d_in[8];
    const float* bo   = (const float*)d_in[9];
    const float* W1   = (const float*)d_in[10];
    const float* b1   = (const float*)d_in[11];
    const float* W2   = (const float*)d_in[12];
    const float* b2   = (const float*)d_in[13];
    const float* Wl   = (const float*)d_in[14];
    const float* bl   = (const float*)d_in[15];
    float* out = (float*)d_out;

    k_idx<<<B, 256>>>(ids);
    k_qh<<<dim3(B, LL), 256>>>(hs0, hs1, ln_g, ln_b);
    k_qp<<<dim3(8, 8, LL), 256>>>(Wq);
    k_kqp<<<dim3(NH, 8, LL), 256>>>(Wk, ln_g, ln_b);
    k_scores<<<dim3(S / 256, B, LL), 256>>>(hs0, hs1);
    k_softmax<<<dim3(NH, B, LL), 256>>>();
    k_ctx<<<dim3(D / 256, B, LL), 256>>>(hs0, hs1, ln_g, ln_b);
    k_ovp<<<dim3(NH, 8, LL), 256>>>(Wv);
    k_wop<<<dim3(8, 8, LL), 256>>>(Wo);
    k_wored<<<128, 256>>>(bo);
    k_mlp1<<<dim3(16, 16), 256>>>(W1);
    k_gelu<<<(B * II) / 256, 256>>>(b1);
    k_mlp2<<<dim3(4, 64), 256>>>(W2);
    k_h2<<<(B * DC) / 256, 256>>>(b2);
    k_logits<<<B * 2, 256>>>(Wl, bl, out);
}